// round 12
// baseline (speedup 1.0000x reference)
#include <cuda_runtime.h>
#include <cuda_bf16.h>
#include <cuda_fp16.h>
#include <stdint.h>

#define NN      100000
#define EE      3200000
#define INDIM   512
#define HIDD    256
#define NCLS    16

// ---------------- static device scratch ------------------------------------
__device__ __half   g_t1h[(size_t)NN * HIDD];     // fp16 t1
__device__ float    g_h [(size_t)NN * HIDD];
__device__ float    g_mulv_pre[NN * 32];
__device__ float    g_mulv    [NN * 32];
__device__ uint32_t g_mask1[(size_t)NN * INDIM / 32];
__device__ uint32_t g_mask2[(size_t)NN * HIDD / 32];
__device__ uint32_t g_mask3[(size_t)NN * HIDD / 32];
__device__ int      g_outdeg[NN];
__device__ int      g_indeg [NN];
__device__ int      g_fill  [NN];
__device__ int      g_off   [NN + 1];
__device__ int      g_csr   [EE];
__device__ float    g_in_is [NN];
__device__ float    g_out_is[NN];
__device__ float    g_part  [512 * 512];
__device__ float    g_stats [512];
// W1 transposed fp16: [16 chunks][256 n][40 k-ushorts (32 data + 8 pad)]
__device__ unsigned short g_W1t[16 * 256 * 40];

// smem layout of k_gemm1_mma (dynamic, bytes): A buf0/1, B buf0/1
#define SA_B(b) ((b) * 10240)
#define SB_B(b) (20480 + (b) * 10240)
#define SM_TOT  40960

#define LDSM4(R, ADDR)                                                         \
    asm volatile("ldmatrix.sync.aligned.m8n8.x4.shared.b16 {%0,%1,%2,%3}, [%4];" \
        : "=r"((R)[0]), "=r"((R)[1]), "=r"((R)[2]), "=r"((R)[3]) : "r"(ADDR))

#define MMAF16(C, A, B0, B1)                                                   \
    asm volatile("mma.sync.aligned.m16n8k16.row.col.f32.f16.f16.f32 "          \
        "{%0,%1,%2,%3}, {%4,%5,%6,%7}, {%8,%9}, {%0,%1,%2,%3};"                \
        : "+f"((C)[0]), "+f"((C)[1]), "+f"((C)[2]), "+f"((C)[3])               \
        : "r"((A)[0]), "r"((A)[1]), "r"((A)[2]), "r"((A)[3]), "r"(B0), "r"(B1))

__device__ __forceinline__ uint32_t smem_u32(const void* p)
{
    uint32_t a;
    asm("{ .reg .u64 t; cvta.to.shared.u64 t, %1; cvt.u32.u64 %0, t; }"
        : "=r"(a) : "l"(p));
    return a;
}

// ---------------- threefry2x32 (JAX-exact core) -----------------------------
__host__ __device__ __forceinline__ uint32_t tf_rot(uint32_t v, int r)
{
#if defined(__CUDA_ARCH__)
    return __funnelshift_l(v, v, r);
#else
    return (v << r) | (v >> (32 - r));
#endif
}

__host__ __device__ __forceinline__ void tf2x32(uint32_t k0, uint32_t k1,
                                                uint32_t x0, uint32_t x1,
                                                uint32_t &o0, uint32_t &o1)
{
    uint32_t ks2 = k0 ^ k1 ^ 0x1BD11BDAu;
#define TF_RND(r) { x0 += x1; x1 = tf_rot(x1, r); x1 ^= x0; }
    x0 += k0; x1 += k1;
    TF_RND(13) TF_RND(15) TF_RND(26) TF_RND(6)
    x0 += k1;  x1 += ks2 + 1u;
    TF_RND(17) TF_RND(29) TF_RND(16) TF_RND(24)
    x0 += ks2; x1 += k0 + 2u;
    TF_RND(13) TF_RND(15) TF_RND(26) TF_RND(6)
    x0 += k0;  x1 += k1 + 3u;
    TF_RND(17) TF_RND(29) TF_RND(16) TF_RND(24)
    x0 += k1;  x1 += ks2 + 4u;
    TF_RND(13) TF_RND(15) TF_RND(26) TF_RND(6)
    x0 += ks2; x1 += k0 + 5u;
    o0 = x0; o1 = x1;
#undef TF_RND
}

__device__ __forceinline__ uint32_t tf_bits(uint32_t k0, uint32_t k1, uint32_t j)
{
    uint32_t o0, o1;
    tf2x32(k0, k1, 0u, j, o0, o1);
    return o0 ^ o1;
}

// ---------------- prep: zero deg arrays + build W1^T fp16 image --------------
__global__ void k_prep(const float* __restrict__ W1)
{
    int i = blockIdx.x * blockDim.x + threadIdx.x;
    if (i < NN) { g_outdeg[i] = 0; g_indeg[i] = 0; g_fill[i] = 0; }
    if (i < INDIM * HIDD) {
        int k = i >> 8, n = i & 255;
        int ch = k >> 5, kk = k & 31;
        int idx = (ch * 256 + n) * 40 + kk;
        g_W1t[idx] = __half_as_ushort(__float2half_rn(W1[i]));
    }
}

__global__ void k_deg(const int* __restrict__ src, const int* __restrict__ dst)
{
    int e = blockIdx.x * blockDim.x + threadIdx.x;
    if (e < EE) {
        atomicAdd(&g_outdeg[src[e]], 1);
        atomicAdd(&g_indeg [dst[e]], 1);
    }
}

__global__ void k_invsqrt()
{
    int i = blockIdx.x * blockDim.x + threadIdx.x;
    if (i < NN) {
        int od = g_outdeg[i]; if (od < 1) od = 1;
        int id = g_indeg [i]; if (id < 1) id = 1;
        g_out_is[i] = rsqrtf((float)od);
        g_in_is [i] = rsqrtf((float)id);
    }
}

__global__ void k_scan()
{
    __shared__ int warpsum[32];
    __shared__ int carry_sh;
    int tid = threadIdx.x, lane = tid & 31, wid = tid >> 5;
    if (tid == 0) carry_sh = 0;
    __syncthreads();
    for (int base = 0; base < NN; base += 1024) {
        int i = base + tid;
        int v = (i < NN) ? g_indeg[i] : 0;
        int incl = v;
#pragma unroll
        for (int o = 1; o < 32; o <<= 1) {
            int n = __shfl_up_sync(0xffffffffu, incl, o);
            if (lane >= o) incl += n;
        }
        if (lane == 31) warpsum[wid] = incl;
        __syncthreads();
        if (wid == 0) {
            int s = warpsum[lane];
#pragma unroll
            for (int o = 1; o < 32; o <<= 1) {
                int n = __shfl_up_sync(0xffffffffu, s, o);
                if (lane >= o) s += n;
            }
            warpsum[lane] = s;
        }
        __syncthreads();
        int wpre = (wid > 0) ? warpsum[wid - 1] : 0;
        int bc = carry_sh;
        if (i < NN) g_off[i] = bc + wpre + incl - v;
        __syncthreads();
        if (tid == 1023) carry_sh = bc + wpre + incl;
        __syncthreads();
    }
    if (threadIdx.x == 0) g_off[NN] = carry_sh;
}

__global__ void k_csrfill(const int* __restrict__ src, const int* __restrict__ dst)
{
    int e = blockIdx.x * blockDim.x + threadIdx.x;
    if (e < EE) {
        int d = dst[e];
        int p = atomicAdd(&g_fill[d], 1);
        g_csr[g_off[d] + p] = src[e];
    }
}

// ---------------- dropout bitmasks -------------------------------------------
__global__ void k_mask1(uint32_t ka, uint32_t kb)
{
    int e = blockIdx.x * blockDim.x + threadIdx.x;
    uint32_t bits = tf_bits(ka, kb, (uint32_t)e);
    uint32_t w = __ballot_sync(0xffffffffu, (int)bits >= 0);
    if ((e & 31) == 0) g_mask1[e >> 5] = w;
}

__global__ void k_mask2(uint32_t a0, uint32_t a1, uint32_t b0, uint32_t b1)
{
    int e = blockIdx.x * blockDim.x + threadIdx.x;
    uint32_t pa = tf_bits(a0, a1, (uint32_t)e);
    uint32_t pb = tf_bits(b0, b1, (uint32_t)e);
    uint32_t w2 = __ballot_sync(0xffffffffu, (int)pa >= 0);
    uint32_t w3 = __ballot_sync(0xffffffffu, (int)pb >= 0);
    if ((e & 31) == 0) {
        g_mask2[e >> 5] = w2;
        g_mask3[e >> 5] = w3;
    }
}

// ---------------- GEMM1 via mma.sync fp16 (single term) ---------------------
__global__ __launch_bounds__(256, 2) void k_gemm1_mma(const float* __restrict__ x)
{
    extern __shared__ char smem[];
    uint32_t sb = smem_u32(smem);
    const int tid  = threadIdx.x;
    const int wid  = tid >> 5;
    const int lane = tid & 31;
    const int bm   = blockIdx.y * 128;
    const int bn   = blockIdx.x;

    const int arow  = tid >> 1;
    const int ahalf = tid & 1;
    int agr = bm + arow; if (agr >= NN) agr = NN - 1;
    int aod = g_outdeg[agr]; if (aod < 1) aod = 1;
    const float as_ = 2.0f * rsqrtf((float)aod);
    const float* axp = x + (size_t)agr * 512 + ahalf * 16;
    const uint32_t aabase = sb + arow * 80 + ahalf * 32;

    const int m0 = (wid & 3) * 32;
    const int n0 = (wid >> 2) * 64;
    const int la_row  = lane & 15;
    const int la_colq = (lane >> 4) * 16;
    const int lb_row  = ((lane >> 4) << 3) + (lane & 7);
    const int lb_colq = ((lane >> 3) & 1) * 16;

#define LOAD_CHUNK(CH, BUF)                                                    \
    {                                                                          \
        int ch_ = (CH);                                                        \
        const float4* xp = reinterpret_cast<const float4*>(axp + ch_ * 32);    \
        uint32_t mw = g_mask1[((size_t)agr * 512 + ch_ * 32) >> 5]             \
                      >> (ahalf * 16);                                         \
        uint32_t h16[8];                                                       \
        _Pragma("unroll")                                                      \
        for (int p = 0; p < 4; p++) {                                          \
            float4 v = xp[p];                                                  \
            float e0 = ((mw >> (4 * p + 0)) & 1u) ? v.x * as_ : 0.f;           \
            float e1 = ((mw >> (4 * p + 1)) & 1u) ? v.y * as_ : 0.f;           \
            float e2 = ((mw >> (4 * p + 2)) & 1u) ? v.z * as_ : 0.f;           \
            float e3 = ((mw >> (4 * p + 3)) & 1u) ? v.w * as_ : 0.f;           \
            __half2 p0 = __floats2half2_rn(e0, e1);                            \
            __half2 p1 = __floats2half2_rn(e2, e3);                            \
            h16[2 * p]     = *reinterpret_cast<uint32_t*>(&p0);                \
            h16[2 * p + 1] = *reinterpret_cast<uint32_t*>(&p1);                \
        }                                                                      \
        uint32_t aa = aabase + SA_B(BUF);                                      \
        asm volatile("st.shared.v4.b32 [%0], {%1,%2,%3,%4};"                   \
            :: "r"(aa),      "r"(h16[0]), "r"(h16[1]), "r"(h16[2]), "r"(h16[3]) : "memory"); \
        asm volatile("st.shared.v4.b32 [%0], {%1,%2,%3,%4};"                   \
            :: "r"(aa + 16), "r"(h16[4]), "r"(h16[5]), "r"(h16[6]), "r"(h16[7]) : "memory"); \
        _Pragma("unroll")                                                      \
        for (int v2 = 0; v2 < 2; v2++) {                                       \
            int unit = tid + 256 * v2;                                         \
            int n = unit >> 2, uu = unit & 3;                                  \
            size_t gsrc = (size_t)((ch_ * 256 + bn * 128 + n) * 40 + uu * 8);  \
            uint4 hv = *reinterpret_cast<const uint4*>(&g_W1t[gsrc]);          \
            uint32_t ba = sb + SB_B(BUF) + n * 80 + uu * 16;                   \
            asm volatile("st.shared.v4.b32 [%0], {%1,%2,%3,%4};"               \
                :: "r"(ba), "r"(hv.x), "r"(hv.y), "r"(hv.z), "r"(hv.w) : "memory"); \
        }                                                                      \
    }

    float c[2][8][4] = {};

    LOAD_CHUNK(0, 0)
    __syncthreads();

    for (int ch = 0; ch < 16; ch++) {
        int buf = ch & 1;
        if (ch + 1 < 16) LOAD_CHUNK(ch + 1, buf ^ 1)

#pragma unroll
        for (int ks = 0; ks < 2; ks++) {
            int kb2 = ks * 32;
            uint32_t ah[2][4];
#pragma unroll
            for (int mt = 0; mt < 2; mt++) {
                uint32_t aaddr = sb + SA_B(buf) +
                    (m0 + mt * 16 + la_row) * 80 + kb2 + la_colq;
                LDSM4(ah[mt], aaddr);
            }
#pragma unroll
            for (int np = 0; np < 4; np++) {
                uint32_t baddr = sb + SB_B(buf) +
                    (n0 + np * 16 + lb_row) * 80 + kb2 + lb_colq;
                uint32_t bh[4];
                LDSM4(bh, baddr);
#pragma unroll
                for (int mt = 0; mt < 2; mt++) {
                    MMAF16(c[mt][2 * np],     ah[mt], bh[0], bh[1]);
                    MMAF16(c[mt][2 * np + 1], ah[mt], bh[2], bh[3]);
                }
            }
        }
        __syncthreads();
    }

    const int g   = lane >> 2;
    const int tig = lane & 3;
#pragma unroll
    for (int mt = 0; mt < 2; mt++) {
#pragma unroll
        for (int nt = 0; nt < 8; nt++) {
            int col = bn * 128 + n0 + nt * 8 + tig * 2;
            int r0 = bm + m0 + mt * 16 + g;
            if (r0 < NN)
                *reinterpret_cast<__half2*>(&g_t1h[(size_t)r0 * 256 + col]) =
                    __floats2half2_rn(c[mt][nt][0], c[mt][nt][1]);
            int r1 = r0 + 8;
            if (r1 < NN)
                *reinterpret_cast<__half2*>(&g_t1h[(size_t)r1 * 256 + col]) =
                    __floats2half2_rn(c[mt][nt][2], c[mt][nt][3]);
        }
    }
#undef LOAD_CHUNK
}

// ---------------- agg1: single pass, fp16 t1, warp covers 256 cols ----------
__global__ void k_agg1()
{
    int gw   = (blockIdx.x * blockDim.x + threadIdx.x) >> 5;
    int lane = threadIdx.x & 31;
    if (gw >= NN) return;
    int beg = g_off[gw], end = g_off[gw + 1];
    float acc[8] = {};
    const uint4* base = reinterpret_cast<const uint4*>(g_t1h) + lane;
    int e = beg;
    for (; e + 1 < end; e += 2) {
        int s0 = __ldg(&g_csr[e]);
        int s1 = __ldg(&g_csr[e + 1]);
        uint4 v0 = base[(size_t)s0 * 32];
        uint4 v1 = base[(size_t)s1 * 32];
        const __half2* h0 = reinterpret_cast<const __half2*>(&v0);
        const __half2* h1 = reinterpret_cast<const __half2*>(&v1);
#pragma unroll
        for (int q = 0; q < 4; q++) {
            float2 f0 = __half22float2(h0[q]);
            float2 f1 = __half22float2(h1[q]);
            acc[2 * q]     += f0.x + f1.x;
            acc[2 * q + 1] += f0.y + f1.y;
        }
    }
    if (e < end) {
        int s0 = __ldg(&g_csr[e]);
        uint4 v0 = base[(size_t)s0 * 32];
        const __half2* h0 = reinterpret_cast<const __half2*>(&v0);
#pragma unroll
        for (int q = 0; q < 4; q++) {
            float2 f0 = __half22float2(h0[q]);
            acc[2 * q]     += f0.x;
            acc[2 * q + 1] += f0.y;
        }
    }
    float sc = g_in_is[gw];
    float4 r0, r1;
    r0.x = fmaxf(acc[0] * sc, 0.f); r0.y = fmaxf(acc[1] * sc, 0.f);
    r0.z = fmaxf(acc[2] * sc, 0.f); r0.w = fmaxf(acc[3] * sc, 0.f);
    r1.x = fmaxf(acc[4] * sc, 0.f); r1.y = fmaxf(acc[5] * sc, 0.f);
    r1.z = fmaxf(acc[6] * sc, 0.f); r1.w = fmaxf(acc[7] * sc, 0.f);
    float* op = &g_h[(size_t)gw * 256 + lane * 8];
    *reinterpret_cast<float4*>(op)     = r0;
    *reinterpret_cast<float4*>(op + 4) = r1;
}

// ---------------- BN stats (deterministic) ----------------------------------
__global__ void k_bnstats()
{
    int c = threadIdx.x;
    float s = 0.f, ss = 0.f;
    for (int r = blockIdx.x; r < NN; r += 512) {
        float v = g_h[(size_t)r * 256 + c];
        s += v;
        ss = fmaf(v, v, ss);
    }
    g_part[blockIdx.x * 512 + c]       = s;
    g_part[blockIdx.x * 512 + 256 + c] = ss;
}

__global__ void k_bnreduce()
{
    int j = blockIdx.x * 256 + threadIdx.x;
    float s = 0.f;
    for (int b = 0; b < 512; b++) s += g_part[b * 512 + j];
    g_stats[j] = s;
}

// ---------------- GEMM2/3 fused with BN + dropout mask arrays ---------------
__global__ __launch_bounds__(256) void k_gemm23(const float* __restrict__ W2,
                                                const float* __restrict__ W3)
{
    __shared__ float sA2[32][68];
    __shared__ float sA3[32][68];
    __shared__ float sB [32][36];
    __shared__ float sMean[256], sIstd[256], sScale[64];
    int tid = threadIdx.x;
    int bm = blockIdx.x * 64;
    int c  = tid & 31;
    int rg = tid >> 5;

    {
        float sum  = g_stats[tid];
        float sums = g_stats[256 + tid];
        float m    = sum * (1.0f / NN);
        float var  = sums * (1.0f / NN) - m * m;
        sMean[tid] = m;
        sIstd[tid] = rsqrtf(var + 1e-5f);
        if (tid < 64) {
            int gr = bm + tid;
            sScale[tid] = 2.0f * g_out_is[gr < NN ? gr : NN - 1];
        }
    }
    __syncthreads();

    float acc[8] = {};
    for (int kt = 0; kt < 256; kt += 32) {
        for (int i = tid; i < 2048; i += 256) {
            int r = i >> 5, k = i & 31;
            int gr = bm + r;
            float a2 = 0.f, a3 = 0.f;
            if (gr < NN) {
                size_t gi = (size_t)gr * 256 + kt + k;
                float hv = g_h[gi];
                float hbn = (hv - sMean[kt + k]) * sIstd[kt + k] * sScale[r];
                uint32_t w2 = g_mask2[gi >> 5];
                uint32_t w3 = g_mask3[gi >> 5];
                a2 = ((w2 >> (k & 31)) & 1u) ? hbn : 0.f;
                a3 = ((w3 >> (k & 31)) & 1u) ? hbn : 0.f;
            }
            sA2[k][r] = a2;
            sA3[k][r] = a3;
        }
        {
            int i = tid;
#pragma unroll
            for (int q = 0; q < 4; q++, i += 256) {
                int k = i >> 5, cc = i & 31;
                int gk = kt + k;
                sB[k][cc] = (cc < 16) ? W2[gk * 16 + cc] : W3[gk * 16 + cc - 16];
            }
        }
        __syncthreads();
        const float* sAx = (c < 16) ? &sA2[0][0] : &sA3[0][0];
#pragma unroll
        for (int kk = 0; kk < 32; kk++) {
            float b = sB[kk][c];
            const float4* pa = reinterpret_cast<const float4*>(sAx + kk * 68 + rg * 8);
            float4 v0 = pa[0], v1 = pa[1];
            acc[0] = fmaf(v0.x, b, acc[0]);
            acc[1] = fmaf(v0.y, b, acc[1]);
            acc[2] = fmaf(v0.z, b, acc[2]);
            acc[3] = fmaf(v0.w, b, acc[3]);
            acc[4] = fmaf(v1.x, b, acc[4]);
            acc[5] = fmaf(v1.y, b, acc[5]);
            acc[6] = fmaf(v1.z, b, acc[6]);
            acc[7] = fmaf(v1.w, b, acc[7]);
        }
        __syncthreads();
    }
#pragma unroll
    for (int i = 0; i < 8; i++) {
        int gr = bm + rg * 8 + i;
        if (gr < NN) g_mulv_pre[gr * 32 + c] = acc[i];
    }
}

// ---------------- agg2 --------------------------------------------------------
__global__ void k_agg2()
{
    int gw   = (blockIdx.x * blockDim.x + threadIdx.x) >> 5;
    int lane = threadIdx.x & 31;
    if (gw >= NN) return;
    int beg = g_off[gw], end = g_off[gw + 1];
    float acc = 0.f;
    int e = beg;
    for (; e + 1 < end; e += 2) {
        int s0 = __ldg(&g_csr[e]);
        int s1 = __ldg(&g_csr[e + 1]);
        acc += g_mulv_pre[s0 * 32 + lane];
        acc += g_mulv_pre[s1 * 32 + lane];
    }
    if (e < end) {
        int s0 = __ldg(&g_csr[e]);
        acc += g_mulv_pre[s0 * 32 + lane];
    }
    g_mulv[gw * 32 + lane] = acc * g_in_is[gw];
}

// ---------------- reparameterize ----------------------------------------------
__global__ void k_reparam(float* __restrict__ out, uint32_t k0, uint32_t k1)
{
    int i = blockIdx.x * blockDim.x + threadIdx.x;
    int e = i * 4;
    if (e >= NN * NCLS) return;
    int row = e >> 4;
    int c   = e & 15;
    const float* mrow = &g_mulv[row * 32];
    float4 mu = *reinterpret_cast<const float4*>(&mrow[c]);
    float4 lv = *reinterpret_cast<const float4*>(&mrow[16 + c]);
    float mus[4] = { mu.x, mu.y, mu.z, mu.w };
    float lvs[4] = { lv.x, lv.y, lv.z, lv.w };
    float r[4];
#pragma unroll
    for (int q = 0; q < 4; q++) {
        uint32_t bits = tf_bits(k0, k1, (uint32_t)(e + q));
        float f = __uint_as_float((bits >> 9) | 0x3f800000u) - 1.0f;
        float u = f * 2.0f - 0.99999994f;
        float eps = 1.4142135623730951f * erfinvf(u);
        r[q] = eps * expf(lvs[q]) + mus[q];
    }
    *reinterpret_cast<float4*>(&out[e]) = make_float4(r[0], r[1], r[2], r[3]);
}

// ---------------- launch --------------------------------------------------------
extern "C" void kernel_launch(void* const* d_in, const int* in_sizes, int n_in,
                              void* d_out, int out_size)
{
    const float* x    = (const float*)d_in[0];
    const float* W1   = (const float*)d_in[1];
    const float* W2   = (const float*)d_in[2];
    const float* W3   = (const float*)d_in[3];
    const int*   esrc = (const int*)d_in[4];
    const int*   edst = (const int*)d_in[5];
    float*       out  = (float*)d_out;

    uint32_t k1a, k1b, k2a0, k2a1, k2b0, k2b1, ke0, ke1;
    tf2x32(0u, 42u, 0u, 0u, k1a,  k1b);
    tf2x32(0u, 42u, 0u, 1u, k2a0, k2a1);
    tf2x32(0u, 42u, 0u, 2u, k2b0, k2b1);
    tf2x32(0u, 42u, 0u, 3u, ke0,  ke1);

    // one-time host-object setup (no device memory involved)
    static cudaStream_t s1 = nullptr, s2 = nullptr;
    static cudaEvent_t evRoot = nullptr, evDeg = nullptr,
                       evG1 = nullptr, evM23 = nullptr;
    if (!s1) {
        cudaStreamCreateWithFlags(&s1, cudaStreamNonBlocking);
        cudaStreamCreateWithFlags(&s2, cudaStreamNonBlocking);
        cudaEventCreateWithFlags(&evRoot, cudaEventDisableTiming);
        cudaEventCreateWithFlags(&evDeg,  cudaEventDisableTiming);
        cudaEventCreateWithFlags(&evG1,   cudaEventDisableTiming);
        cudaEventCreateWithFlags(&evM23,  cudaEventDisableTiming);
        cudaFuncSetAttribute(k_gemm1_mma,
                             cudaFuncAttributeMaxDynamicSharedMemorySize, SM_TOT);
    }

    // fork
    cudaEventRecord(evRoot, 0);
    cudaStreamWaitEvent(s1, evRoot, 0);
    cudaStreamWaitEvent(s2, evRoot, 0);

    // s1: mask1 -> (wait deg) -> gemm1
    k_mask1<<<NN * INDIM / 256, 256, 0, s1>>>(k1a, k1b);
    // s2: mask2/3
    k_mask2<<<NN * HIDD / 256, 256, 0, s2>>>(k2a0, k2a1, k2b0, k2b1);
    cudaEventRecord(evM23, s2);

    // main: prep -> deg
    k_prep<<<(INDIM * HIDD) / 256, 256>>>(W1);
    k_deg <<<EE / 256, 256>>>(esrc, edst);
    cudaEventRecord(evDeg, 0);

    cudaStreamWaitEvent(s1, evDeg, 0);
    dim3 g1(2, (NN + 127) / 128);
    k_gemm1_mma<<<g1, 256, SM_TOT, s1>>>(x);
    cudaEventRecord(evG1, s1);

    // main: CSR build in parallel with gemm1
    k_invsqrt<<<(NN + 255) / 256, 256>>>();
    k_scan   <<<1, 1024>>>();
    k_csrfill<<<EE / 256, 256>>>(esrc, edst);

    // join gemm1, then aggregate
    cudaStreamWaitEvent(0, evG1, 0);
    k_agg1   <<<(NN * 32) / 256, 256>>>();

    k_bnstats <<<512, 256>>>();
    k_bnreduce<<<2, 256>>>();

    // join mask2/3, then output head
    cudaStreamWaitEvent(0, evM23, 0);
    k_gemm23 <<<(NN + 63) / 64, 256>>>(W2, W3);
    k_agg2   <<<(NN * 32) / 256, 256>>>();

    k_reparam<<<(NN * NCLS / 4 + 255) / 256, 256>>>(out, ke0, ke1);
}

// round 13
// speedup vs baseline: 1.0890x; 1.0890x over previous
#include <cuda_runtime.h>
#include <cuda_bf16.h>
#include <cuda_fp16.h>
#include <stdint.h>

#define NN      100000
#define EE      3200000
#define INDIM   512
#define HIDD    256
#define NCLS    16
#define SCAN_B  98            // ceil(NN/1024)

// ---------------- static device scratch ------------------------------------
__device__ __half   g_t1h[(size_t)NN * HIDD];     // fp16 t1
__device__ __half   g_h2 [(size_t)NN * HIDD];     // fp16 h (post BN-input)
__device__ float    g_mulv_pre[NN * 32];
__device__ float    g_mulv    [NN * 32];
__device__ uint32_t g_mask1[(size_t)NN * INDIM / 32];
__device__ int      g_outdeg[NN];
__device__ int      g_indeg [NN];
__device__ int      g_fill  [NN];
__device__ int      g_off   [NN + 1];
__device__ int      g_bsum  [SCAN_B];
__device__ int      g_csr   [EE];
__device__ float    g_in_is [NN];
__device__ float    g_out_is[NN];
__device__ float    g_part  [512 * 512];
__device__ float    g_stats [512];
// W1 transposed fp16: [16 chunks][256 n][40 k-ushorts (32 data + 8 pad)]
__device__ unsigned short g_W1t[16 * 256 * 40];

// smem layout of k_gemm1_mma (dynamic, bytes): A buf0/1, B buf0/1
#define SA_B(b) ((b) * 10240)
#define SB_B(b) (20480 + (b) * 10240)
#define SM_TOT  40960

#define LDSM4(R, ADDR)                                                         \
    asm volatile("ldmatrix.sync.aligned.m8n8.x4.shared.b16 {%0,%1,%2,%3}, [%4];" \
        : "=r"((R)[0]), "=r"((R)[1]), "=r"((R)[2]), "=r"((R)[3]) : "r"(ADDR))

#define MMAF16(C, A, B0, B1)                                                   \
    asm volatile("mma.sync.aligned.m16n8k16.row.col.f32.f16.f16.f32 "          \
        "{%0,%1,%2,%3}, {%4,%5,%6,%7}, {%8,%9}, {%0,%1,%2,%3};"                \
        : "+f"((C)[0]), "+f"((C)[1]), "+f"((C)[2]), "+f"((C)[3])               \
        : "r"((A)[0]), "r"((A)[1]), "r"((A)[2]), "r"((A)[3]), "r"(B0), "r"(B1))

__device__ __forceinline__ uint32_t smem_u32(const void* p)
{
    uint32_t a;
    asm("{ .reg .u64 t; cvta.to.shared.u64 t, %1; cvt.u32.u64 %0, t; }"
        : "=r"(a) : "l"(p));
    return a;
}

// ---------------- threefry2x32 (JAX-exact core) -----------------------------
__host__ __device__ __forceinline__ uint32_t tf_rot(uint32_t v, int r)
{
#if defined(__CUDA_ARCH__)
    return __funnelshift_l(v, v, r);
#else
    return (v << r) | (v >> (32 - r));
#endif
}

__host__ __device__ __forceinline__ void tf2x32(uint32_t k0, uint32_t k1,
                                                uint32_t x0, uint32_t x1,
                                                uint32_t &o0, uint32_t &o1)
{
    uint32_t ks2 = k0 ^ k1 ^ 0x1BD11BDAu;
#define TF_RND(r) { x0 += x1; x1 = tf_rot(x1, r); x1 ^= x0; }
    x0 += k0; x1 += k1;
    TF_RND(13) TF_RND(15) TF_RND(26) TF_RND(6)
    x0 += k1;  x1 += ks2 + 1u;
    TF_RND(17) TF_RND(29) TF_RND(16) TF_RND(24)
    x0 += ks2; x1 += k0 + 2u;
    TF_RND(13) TF_RND(15) TF_RND(26) TF_RND(6)
    x0 += k0;  x1 += k1 + 3u;
    TF_RND(17) TF_RND(29) TF_RND(16) TF_RND(24)
    x0 += k1;  x1 += ks2 + 4u;
    TF_RND(13) TF_RND(15) TF_RND(26) TF_RND(6)
    x0 += ks2; x1 += k0 + 5u;
    o0 = x0; o1 = x1;
#undef TF_RND
}

__device__ __forceinline__ uint32_t tf_bits(uint32_t k0, uint32_t k1, uint32_t j)
{
    uint32_t o0, o1;
    tf2x32(k0, k1, 0u, j, o0, o1);
    return o0 ^ o1;
}

// ---------------- prep: zero deg arrays + build W1^T fp16 image --------------
__global__ void k_prep(const float* __restrict__ W1)
{
    int i = blockIdx.x * blockDim.x + threadIdx.x;
    if (i < NN) { g_outdeg[i] = 0; g_indeg[i] = 0; g_fill[i] = 0; }
    if (i < INDIM * HIDD) {
        int k = i >> 8, n = i & 255;
        int ch = k >> 5, kk = k & 31;
        int idx = (ch * 256 + n) * 40 + kk;
        g_W1t[idx] = __half_as_ushort(__float2half_rn(W1[i]));
    }
}

__global__ void k_deg(const int* __restrict__ src, const int* __restrict__ dst)
{
    int e = blockIdx.x * blockDim.x + threadIdx.x;
    if (e < EE) {
        atomicAdd(&g_outdeg[src[e]], 1);
        atomicAdd(&g_indeg [dst[e]], 1);
    }
}

// ---------------- multi-block scan of indeg -> g_off -------------------------
// phase 1: per-block (1024) exclusive scan into g_off, block total to g_bsum
__global__ void k_scan1()
{
    __shared__ int warpsum[32];
    int tid = threadIdx.x, lane = tid & 31, wid = tid >> 5;
    int i = blockIdx.x * 1024 + tid;
    int v = (i < NN) ? g_indeg[i] : 0;
    int incl = v;
#pragma unroll
    for (int o = 1; o < 32; o <<= 1) {
        int n = __shfl_up_sync(0xffffffffu, incl, o);
        if (lane >= o) incl += n;
    }
    if (lane == 31) warpsum[wid] = incl;
    __syncthreads();
    if (wid == 0) {
        int s = warpsum[lane];
#pragma unroll
        for (int o = 1; o < 32; o <<= 1) {
            int n = __shfl_up_sync(0xffffffffu, s, o);
            if (lane >= o) s += n;
        }
        warpsum[lane] = s;
    }
    __syncthreads();
    int wpre = (wid > 0) ? warpsum[wid - 1] : 0;
    if (i < NN) g_off[i] = wpre + incl - v;      // block-local exclusive
    if (tid == 1023) g_bsum[blockIdx.x] = wpre + incl;
}

// phase 2: single warp-ish block scans the 98 block sums (exclusive)
__global__ void k_scan2()
{
    __shared__ int sh[SCAN_B];
    int tid = threadIdx.x;               // 128 threads
    int v = (tid < SCAN_B) ? g_bsum[tid] : 0;
    if (tid < SCAN_B) sh[tid] = v;
    __syncthreads();
    if (tid == 0) {
        int run = 0;
        for (int b = 0; b < SCAN_B; b++) {
            int t = sh[b];
            sh[b] = run;
            run += t;
        }
        g_off[NN] = run;
    }
    __syncthreads();
    if (tid < SCAN_B) g_bsum[tid] = sh[tid];
}

// phase 3: add block offsets + compute inv-sqrt degrees
__global__ void k_scan3()
{
    int i = blockIdx.x * blockDim.x + threadIdx.x;
    if (i < NN) {
        g_off[i] += g_bsum[i >> 10];
        int od = g_outdeg[i]; if (od < 1) od = 1;
        int id = g_indeg [i]; if (id < 1) id = 1;
        g_out_is[i] = rsqrtf((float)od);
        g_in_is [i] = rsqrtf((float)id);
    }
}

__global__ void k_csrfill(const int* __restrict__ src, const int* __restrict__ dst)
{
    int e = blockIdx.x * blockDim.x + threadIdx.x;
    if (e < EE) {
        int d = dst[e];
        int p = atomicAdd(&g_fill[d], 1);
        g_csr[g_off[d] + p] = src[e];
    }
}

// ---------------- dropout bitmask for layer 1 --------------------------------
__global__ void k_mask1(uint32_t ka, uint32_t kb)
{
    int e = blockIdx.x * blockDim.x + threadIdx.x;
    uint32_t bits = tf_bits(ka, kb, (uint32_t)e);
    uint32_t w = __ballot_sync(0xffffffffu, (int)bits >= 0);
    if ((e & 31) == 0) g_mask1[e >> 5] = w;
}

// ---------------- GEMM1 via mma.sync fp16 (single term) ---------------------
__global__ __launch_bounds__(256, 2) void k_gemm1_mma(const float* __restrict__ x)
{
    extern __shared__ char smem[];
    uint32_t sb = smem_u32(smem);
    const int tid  = threadIdx.x;
    const int wid  = tid >> 5;
    const int lane = tid & 31;
    const int bm   = blockIdx.y * 128;
    const int bn   = blockIdx.x;

    const int arow  = tid >> 1;
    const int ahalf = tid & 1;
    int agr = bm + arow; if (agr >= NN) agr = NN - 1;
    int aod = g_outdeg[agr]; if (aod < 1) aod = 1;
    const float as_ = 2.0f * rsqrtf((float)aod);
    const float* axp = x + (size_t)agr * 512 + ahalf * 16;
    const uint32_t aabase = sb + arow * 80 + ahalf * 32;

    const int m0 = (wid & 3) * 32;
    const int n0 = (wid >> 2) * 64;
    const int la_row  = lane & 15;
    const int la_colq = (lane >> 4) * 16;
    const int lb_row  = ((lane >> 4) << 3) + (lane & 7);
    const int lb_colq = ((lane >> 3) & 1) * 16;

#define LOAD_CHUNK(CH, BUF)                                                    \
    {                                                                          \
        int ch_ = (CH);                                                        \
        const float4* xp = reinterpret_cast<const float4*>(axp + ch_ * 32);    \
        uint32_t mw = g_mask1[((size_t)agr * 512 + ch_ * 32) >> 5]             \
                      >> (ahalf * 16);                                         \
        uint32_t h16[8];                                                       \
        _Pragma("unroll")                                                      \
        for (int p = 0; p < 4; p++) {                                          \
            float4 v = xp[p];                                                  \
            float e0 = ((mw >> (4 * p + 0)) & 1u) ? v.x * as_ : 0.f;           \
            float e1 = ((mw >> (4 * p + 1)) & 1u) ? v.y * as_ : 0.f;           \
            float e2 = ((mw >> (4 * p + 2)) & 1u) ? v.z * as_ : 0.f;           \
            float e3 = ((mw >> (4 * p + 3)) & 1u) ? v.w * as_ : 0.f;           \
            __half2 p0 = __floats2half2_rn(e0, e1);                            \
            __half2 p1 = __floats2half2_rn(e2, e3);                            \
            h16[2 * p]     = *reinterpret_cast<uint32_t*>(&p0);                \
            h16[2 * p + 1] = *reinterpret_cast<uint32_t*>(&p1);                \
        }                                                                      \
        uint32_t aa = aabase + SA_B(BUF);                                      \
        asm volatile("st.shared.v4.b32 [%0], {%1,%2,%3,%4};"                   \
            :: "r"(aa),      "r"(h16[0]), "r"(h16[1]), "r"(h16[2]), "r"(h16[3]) : "memory"); \
        asm volatile("st.shared.v4.b32 [%0], {%1,%2,%3,%4};"                   \
            :: "r"(aa + 16), "r"(h16[4]), "r"(h16[5]), "r"(h16[6]), "r"(h16[7]) : "memory"); \
        _Pragma("unroll")                                                      \
        for (int v2 = 0; v2 < 2; v2++) {                                       \
            int unit = tid + 256 * v2;                                         \
            int n = unit >> 2, uu = unit & 3;                                  \
            size_t gsrc = (size_t)((ch_ * 256 + bn * 128 + n) * 40 + uu * 8);  \
            uint4 hv = *reinterpret_cast<const uint4*>(&g_W1t[gsrc]);          \
            uint32_t ba = sb + SB_B(BUF) + n * 80 + uu * 16;                   \
            asm volatile("st.shared.v4.b32 [%0], {%1,%2,%3,%4};"               \
                :: "r"(ba), "r"(hv.x), "r"(hv.y), "r"(hv.z), "r"(hv.w) : "memory"); \
        }                                                                      \
    }

    float c[2][8][4] = {};

    LOAD_CHUNK(0, 0)
    __syncthreads();

    for (int ch = 0; ch < 16; ch++) {
        int buf = ch & 1;
        if (ch + 1 < 16) LOAD_CHUNK(ch + 1, buf ^ 1)

#pragma unroll
        for (int ks = 0; ks < 2; ks++) {
            int kb2 = ks * 32;
            uint32_t ah[2][4];
#pragma unroll
            for (int mt = 0; mt < 2; mt++) {
                uint32_t aaddr = sb + SA_B(buf) +
                    (m0 + mt * 16 + la_row) * 80 + kb2 + la_colq;
                LDSM4(ah[mt], aaddr);
            }
#pragma unroll
            for (int np = 0; np < 4; np++) {
                uint32_t baddr = sb + SB_B(buf) +
                    (n0 + np * 16 + lb_row) * 80 + kb2 + lb_colq;
                uint32_t bh[4];
                LDSM4(bh, baddr);
#pragma unroll
                for (int mt = 0; mt < 2; mt++) {
                    MMAF16(c[mt][2 * np],     ah[mt], bh[0], bh[1]);
                    MMAF16(c[mt][2 * np + 1], ah[mt], bh[2], bh[3]);
                }
            }
        }
        __syncthreads();
    }

    const int g   = lane >> 2;
    const int tig = lane & 3;
#pragma unroll
    for (int mt = 0; mt < 2; mt++) {
#pragma unroll
        for (int nt = 0; nt < 8; nt++) {
            int col = bn * 128 + n0 + nt * 8 + tig * 2;
            int r0 = bm + m0 + mt * 16 + g;
            if (r0 < NN)
                *reinterpret_cast<__half2*>(&g_t1h[(size_t)r0 * 256 + col]) =
                    __floats2half2_rn(c[mt][nt][0], c[mt][nt][1]);
            int r1 = r0 + 8;
            if (r1 < NN)
                *reinterpret_cast<__half2*>(&g_t1h[(size_t)r1 * 256 + col]) =
                    __floats2half2_rn(c[mt][nt][2], c[mt][nt][3]);
        }
    }
#undef LOAD_CHUNK
}

// ---------------- agg1: single pass fp16 in, fp16 h out ----------------------
__global__ void k_agg1()
{
    int gw   = (blockIdx.x * blockDim.x + threadIdx.x) >> 5;
    int lane = threadIdx.x & 31;
    if (gw >= NN) return;
    int beg = g_off[gw], end = g_off[gw + 1];
    float acc[8] = {};
    const uint4* base = reinterpret_cast<const uint4*>(g_t1h) + lane;
    int e = beg;
    for (; e + 1 < end; e += 2) {
        int s0 = __ldg(&g_csr[e]);
        int s1 = __ldg(&g_csr[e + 1]);
        uint4 v0 = base[(size_t)s0 * 32];
        uint4 v1 = base[(size_t)s1 * 32];
        const __half2* h0 = reinterpret_cast<const __half2*>(&v0);
        const __half2* h1 = reinterpret_cast<const __half2*>(&v1);
#pragma unroll
        for (int q = 0; q < 4; q++) {
            float2 f0 = __half22float2(h0[q]);
            float2 f1 = __half22float2(h1[q]);
            acc[2 * q]     += f0.x + f1.x;
            acc[2 * q + 1] += f0.y + f1.y;
        }
    }
    if (e < end) {
        int s0 = __ldg(&g_csr[e]);
        uint4 v0 = base[(size_t)s0 * 32];
        const __half2* h0 = reinterpret_cast<const __half2*>(&v0);
#pragma unroll
        for (int q = 0; q < 4; q++) {
            float2 f0 = __half22float2(h0[q]);
            acc[2 * q]     += f0.x;
            acc[2 * q + 1] += f0.y;
        }
    }
    float sc = g_in_is[gw];
    __half2 o[4];
#pragma unroll
    for (int q = 0; q < 4; q++)
        o[q] = __floats2half2_rn(fmaxf(acc[2 * q] * sc, 0.f),
                                 fmaxf(acc[2 * q + 1] * sc, 0.f));
    *reinterpret_cast<uint4*>(&g_h2[(size_t)gw * 256 + lane * 8]) =
        *reinterpret_cast<uint4*>(o);
}

// ---------------- BN stats (deterministic, fp16 h) ---------------------------
__global__ void k_bnstats()
{
    int c = threadIdx.x;
    float s = 0.f, ss = 0.f;
    for (int r = blockIdx.x; r < NN; r += 512) {
        float v = __half2float(g_h2[(size_t)r * 256 + c]);
        s += v;
        ss = fmaf(v, v, ss);
    }
    g_part[blockIdx.x * 512 + c]       = s;
    g_part[blockIdx.x * 512 + 256 + c] = ss;
}

__global__ void k_bnreduce()
{
    int j = blockIdx.x * 256 + threadIdx.x;
    float s = 0.f;
    for (int b = 0; b < 512; b++) s += g_part[b * 512 + j];
    g_stats[j] = s;
}

// ---------------- GEMM2/3 fused with BN + inline dropout (threefry) ---------
__global__ __launch_bounds__(256) void k_gemm23(const float* __restrict__ W2,
                                                const float* __restrict__ W3,
                                                uint32_t a0, uint32_t a1,
                                                uint32_t b0, uint32_t b1)
{
    __shared__ float sA2[32][68];
    __shared__ float sA3[32][68];
    __shared__ float sB [32][36];
    __shared__ float sMean[256], sIstd[256], sScale[64];
    int tid = threadIdx.x;
    int bm = blockIdx.x * 64;
    int c  = tid & 31;
    int rg = tid >> 5;

    {
        float sum  = g_stats[tid];
        float sums = g_stats[256 + tid];
        float m    = sum * (1.0f / NN);
        float var  = sums * (1.0f / NN) - m * m;
        sMean[tid] = m;
        sIstd[tid] = rsqrtf(var + 1e-5f);
        if (tid < 64) {
            int gr = bm + tid;
            sScale[tid] = 2.0f * g_out_is[gr < NN ? gr : NN - 1];
        }
    }
    __syncthreads();

    float acc[8] = {};
    for (int kt = 0; kt < 256; kt += 32) {
        for (int i = tid; i < 2048; i += 256) {
            int r = i >> 5, k = i & 31;
            int gr = bm + r;
            float a2 = 0.f, a3 = 0.f;
            if (gr < NN) {
                uint32_t gi = (uint32_t)gr * 256 + kt + k;
                float hv = __half2float(g_h2[gi]);
                float hbn = (hv - sMean[kt + k]) * sIstd[kt + k] * sScale[r];
                uint32_t pa = tf_bits(a0, a1, gi);
                uint32_t pb = tf_bits(b0, b1, gi);
                a2 = ((int)pa >= 0) ? hbn : 0.f;
                a3 = ((int)pb >= 0) ? hbn : 0.f;
            }
            sA2[k][r] = a2;
            sA3[k][r] = a3;
        }
        {
            int i = tid;
#pragma unroll
            for (int q = 0; q < 4; q++, i += 256) {
                int k = i >> 5, cc = i & 31;
                int gk = kt + k;
                sB[k][cc] = (cc < 16) ? W2[gk * 16 + cc] : W3[gk * 16 + cc - 16];
            }
        }
        __syncthreads();
        const float* sAx = (c < 16) ? &sA2[0][0] : &sA3[0][0];
#pragma unroll
        for (int kk = 0; kk < 32; kk++) {
            float b = sB[kk][c];
            const float4* pa = reinterpret_cast<const float4*>(sAx + kk * 68 + rg * 8);
            float4 v0 = pa[0], v1 = pa[1];
            acc[0] = fmaf(v0.x, b, acc[0]);
            acc[1] = fmaf(v0.y, b, acc[1]);
            acc[2] = fmaf(v0.z, b, acc[2]);
            acc[3] = fmaf(v0.w, b, acc[3]);
            acc[4] = fmaf(v1.x, b, acc[4]);
            acc[5] = fmaf(v1.y, b, acc[5]);
            acc[6] = fmaf(v1.z, b, acc[6]);
            acc[7] = fmaf(v1.w, b, acc[7]);
        }
        __syncthreads();
    }
#pragma unroll
    for (int i = 0; i < 8; i++) {
        int gr = bm + rg * 8 + i;
        if (gr < NN) g_mulv_pre[gr * 32 + c] = acc[i];
    }
}

// ---------------- agg2 --------------------------------------------------------
__global__ void k_agg2()
{
    int gw   = (blockIdx.x * blockDim.x + threadIdx.x) >> 5;
    int lane = threadIdx.x & 31;
    if (gw >= NN) return;
    int beg = g_off[gw], end = g_off[gw + 1];
    float acc = 0.f;
    int e = beg;
    for (; e + 1 < end; e += 2) {
        int s0 = __ldg(&g_csr[e]);
        int s1 = __ldg(&g_csr[e + 1]);
        acc += g_mulv_pre[s0 * 32 + lane];
        acc += g_mulv_pre[s1 * 32 + lane];
    }
    if (e < end) {
        int s0 = __ldg(&g_csr[e]);
        acc += g_mulv_pre[s0 * 32 + lane];
    }
    g_mulv[gw * 32 + lane] = acc * g_in_is[gw];
}

// ---------------- reparameterize ----------------------------------------------
__global__ void k_reparam(float* __restrict__ out, uint32_t k0, uint32_t k1)
{
    int i = blockIdx.x * blockDim.x + threadIdx.x;
    int e = i * 4;
    if (e >= NN * NCLS) return;
    int row = e >> 4;
    int c   = e & 15;
    const float* mrow = &g_mulv[row * 32];
    float4 mu = *reinterpret_cast<const float4*>(&mrow[c]);
    float4 lv = *reinterpret_cast<const float4*>(&mrow[16 + c]);
    float mus[4] = { mu.x, mu.y, mu.z, mu.w };
    float lvs[4] = { lv.x, lv.y, lv.z, lv.w };
    float r[4];
#pragma unroll
    for (int q = 0; q < 4; q++) {
        uint32_t bits = tf_bits(k0, k1, (uint32_t)(e + q));
        float f = __uint_as_float((bits >> 9) | 0x3f800000u) - 1.0f;
        float u = f * 2.0f - 0.99999994f;
        float eps = 1.4142135623730951f * erfinvf(u);
        r[q] = eps * expf(lvs[q]) + mus[q];
    }
    *reinterpret_cast<float4*>(&out[e]) = make_float4(r[0], r[1], r[2], r[3]);
}

// ---------------- launch --------------------------------------------------------
extern "C" void kernel_launch(void* const* d_in, const int* in_sizes, int n_in,
                              void* d_out, int out_size)
{
    const float* x    = (const float*)d_in[0];
    const float* W1   = (const float*)d_in[1];
    const float* W2   = (const float*)d_in[2];
    const float* W3   = (const float*)d_in[3];
    const int*   esrc = (const int*)d_in[4];
    const int*   edst = (const int*)d_in[5];
    float*       out  = (float*)d_out;

    uint32_t k1a, k1b, k2a0, k2a1, k2b0, k2b1, ke0, ke1;
    tf2x32(0u, 42u, 0u, 0u, k1a,  k1b);
    tf2x32(0u, 42u, 0u, 1u, k2a0, k2a1);
    tf2x32(0u, 42u, 0u, 2u, k2b0, k2b1);
    tf2x32(0u, 42u, 0u, 3u, ke0,  ke1);

    cudaFuncSetAttribute(k_gemm1_mma,
                         cudaFuncAttributeMaxDynamicSharedMemorySize, SM_TOT);

    k_prep   <<<(INDIM * HIDD) / 256, 256>>>(W1);
    k_deg    <<<EE / 256, 256>>>(esrc, edst);
    k_mask1  <<<NN * INDIM / 256, 256>>>(k1a, k1b);

    dim3 g1(2, (NN + 127) / 128);
    k_gemm1_mma<<<g1, 256, SM_TOT>>>(x);             // 4th -> profiled slot

    k_scan1  <<<SCAN_B, 1024>>>();
    k_scan2  <<<1, 128>>>();
    k_scan3  <<<(NN + 1023) / 1024, 1024>>>();
    k_csrfill<<<EE / 256, 256>>>(esrc, edst);

    k_agg1   <<<(NN * 32) / 256, 256>>>();

    k_bnstats <<<512, 256>>>();
    k_bnreduce<<<2, 256>>>();

    k_gemm23 <<<(NN + 63) / 64, 256>>>(W2, W3, k2a0, k2a1, k2b0, k2b1);
    k_agg2   <<<(NN * 32) / 256, 256>>>();

    k_reparam<<<(NN * NCLS / 4 + 255) / 256, 256>>>(out, ke0, ke1);
}

// round 14
// speedup vs baseline: 1.1454x; 1.0517x over previous
#include <cuda_runtime.h>
#include <cuda_bf16.h>
#include <cuda_fp16.h>
#include <stdint.h>

#define NN      100000
#define EE      3200000
#define INDIM   512
#define HIDD    256
#define NCLS    16
#define SCAN_B  98            // ceil(NN/1024)

// ---------------- static device scratch ------------------------------------
__device__ __half   g_t1h[(size_t)NN * HIDD];     // fp16 t1
__device__ __half   g_h2 [(size_t)NN * HIDD];     // fp16 h
__device__ float    g_mulv_pre[NN * 32];
__device__ float    g_mulv    [NN * 32];
__device__ uint32_t g_mask1[(size_t)NN * INDIM / 32];
__device__ uint32_t g_mask2[(size_t)NN * HIDD / 32];
__device__ uint32_t g_mask3[(size_t)NN * HIDD / 32];
__device__ int      g_outdeg[NN];
__device__ int      g_indeg [NN];
__device__ int      g_fill  [NN];
__device__ int      g_off   [NN + 1];
__device__ int      g_bsum  [SCAN_B];
__device__ int      g_csr   [EE];
__device__ float    g_in_is [NN];
__device__ float    g_out_is[NN];
__device__ float    g_part  [512 * 512];
__device__ float    g_stats [512];
// W1 transposed fp16: [16 chunks][256 n][40 k-ushorts (32 data + 8 pad)]
__device__ unsigned short g_W1t[16 * 256 * 40];

// smem layout of k_gemm1_mma (dynamic, bytes): A buf0/1, B buf0/1
#define SA_B(b) ((b) * 10240)
#define SB_B(b) (20480 + (b) * 10240)
#define SM_TOT  40960

#define LDSM4(R, ADDR)                                                         \
    asm volatile("ldmatrix.sync.aligned.m8n8.x4.shared.b16 {%0,%1,%2,%3}, [%4];" \
        : "=r"((R)[0]), "=r"((R)[1]), "=r"((R)[2]), "=r"((R)[3]) : "r"(ADDR))

#define MMAF16(C, A, B0, B1)                                                   \
    asm volatile("mma.sync.aligned.m16n8k16.row.col.f32.f16.f16.f32 "          \
        "{%0,%1,%2,%3}, {%4,%5,%6,%7}, {%8,%9}, {%0,%1,%2,%3};"                \
        : "+f"((C)[0]), "+f"((C)[1]), "+f"((C)[2]), "+f"((C)[3])               \
        : "r"((A)[0]), "r"((A)[1]), "r"((A)[2]), "r"((A)[3]), "r"(B0), "r"(B1))

__device__ __forceinline__ uint32_t smem_u32(const void* p)
{
    uint32_t a;
    asm("{ .reg .u64 t; cvta.to.shared.u64 t, %1; cvt.u32.u64 %0, t; }"
        : "=r"(a) : "l"(p));
    return a;
}

// ---------------- threefry2x32 (JAX-exact core) -----------------------------
__host__ __device__ __forceinline__ uint32_t tf_rot(uint32_t v, int r)
{
#if defined(__CUDA_ARCH__)
    return __funnelshift_l(v, v, r);
#else
    return (v << r) | (v >> (32 - r));
#endif
}

__host__ __device__ __forceinline__ void tf2x32(uint32_t k0, uint32_t k1,
                                                uint32_t x0, uint32_t x1,
                                                uint32_t &o0, uint32_t &o1)
{
    uint32_t ks2 = k0 ^ k1 ^ 0x1BD11BDAu;
#define TF_RND(r) { x0 += x1; x1 = tf_rot(x1, r); x1 ^= x0; }
    x0 += k0; x1 += k1;
    TF_RND(13) TF_RND(15) TF_RND(26) TF_RND(6)
    x0 += k1;  x1 += ks2 + 1u;
    TF_RND(17) TF_RND(29) TF_RND(16) TF_RND(24)
    x0 += ks2; x1 += k0 + 2u;
    TF_RND(13) TF_RND(15) TF_RND(26) TF_RND(6)
    x0 += k0;  x1 += k1 + 3u;
    TF_RND(17) TF_RND(29) TF_RND(16) TF_RND(24)
    x0 += k1;  x1 += ks2 + 4u;
    TF_RND(13) TF_RND(15) TF_RND(26) TF_RND(6)
    x0 += ks2; x1 += k0 + 5u;
    o0 = x0; o1 = x1;
#undef TF_RND
}

__device__ __forceinline__ uint32_t tf_bits(uint32_t k0, uint32_t k1, uint32_t j)
{
    uint32_t o0, o1;
    tf2x32(k0, k1, 0u, j, o0, o1);
    return o0 ^ o1;
}

// ---------------- prep: zero deg arrays + build W1^T fp16 image --------------
__global__ void k_prep(const float* __restrict__ W1)
{
    int i = blockIdx.x * blockDim.x + threadIdx.x;
    if (i < NN) { g_outdeg[i] = 0; g_indeg[i] = 0; g_fill[i] = 0; }
    if (i < INDIM * HIDD) {
        int k = i >> 8, n = i & 255;
        int ch = k >> 5, kk = k & 31;
        int idx = (ch * 256 + n) * 40 + kk;
        g_W1t[idx] = __half_as_ushort(__float2half_rn(W1[i]));
    }
}

__global__ void k_deg(const int* __restrict__ src, const int* __restrict__ dst)
{
    int e = blockIdx.x * blockDim.x + threadIdx.x;
    if (e < EE) {
        atomicAdd(&g_outdeg[src[e]], 1);
        atomicAdd(&g_indeg [dst[e]], 1);
    }
}

// ---------------- multi-block scan of indeg -> g_off -------------------------
__global__ void k_scan1()
{
    __shared__ int warpsum[32];
    int tid = threadIdx.x, lane = tid & 31, wid = tid >> 5;
    int i = blockIdx.x * 1024 + tid;
    int v = (i < NN) ? g_indeg[i] : 0;
    int incl = v;
#pragma unroll
    for (int o = 1; o < 32; o <<= 1) {
        int n = __shfl_up_sync(0xffffffffu, incl, o);
        if (lane >= o) incl += n;
    }
    if (lane == 31) warpsum[wid] = incl;
    __syncthreads();
    if (wid == 0) {
        int s = warpsum[lane];
#pragma unroll
        for (int o = 1; o < 32; o <<= 1) {
            int n = __shfl_up_sync(0xffffffffu, s, o);
            if (lane >= o) s += n;
        }
        warpsum[lane] = s;
    }
    __syncthreads();
    int wpre = (wid > 0) ? warpsum[wid - 1] : 0;
    if (i < NN) g_off[i] = wpre + incl - v;
    if (tid == 1023) g_bsum[blockIdx.x] = wpre + incl;
}

__global__ void k_scan2()
{
    __shared__ int sh[SCAN_B];
    int tid = threadIdx.x;
    int v = (tid < SCAN_B) ? g_bsum[tid] : 0;
    if (tid < SCAN_B) sh[tid] = v;
    __syncthreads();
    if (tid == 0) {
        int run = 0;
        for (int b = 0; b < SCAN_B; b++) {
            int t = sh[b];
            sh[b] = run;
            run += t;
        }
        g_off[NN] = run;
    }
    __syncthreads();
    if (tid < SCAN_B) g_bsum[tid] = sh[tid];
}

__global__ void k_scan3()
{
    int i = blockIdx.x * blockDim.x + threadIdx.x;
    if (i < NN) {
        g_off[i] += g_bsum[i >> 10];
        int od = g_outdeg[i]; if (od < 1) od = 1;
        int id = g_indeg [i]; if (id < 1) id = 1;
        g_out_is[i] = rsqrtf((float)od);
        g_in_is [i] = rsqrtf((float)id);
    }
}

__global__ void k_csrfill(const int* __restrict__ src, const int* __restrict__ dst)
{
    int e = blockIdx.x * blockDim.x + threadIdx.x;
    if (e < EE) {
        int d = dst[e];
        int p = atomicAdd(&g_fill[d], 1);
        g_csr[g_off[d] + p] = src[e];
    }
}

// ---------------- dropout bitmasks -------------------------------------------
__global__ void k_mask1(uint32_t ka, uint32_t kb)
{
    int e = blockIdx.x * blockDim.x + threadIdx.x;
    uint32_t bits = tf_bits(ka, kb, (uint32_t)e);
    uint32_t w = __ballot_sync(0xffffffffu, (int)bits >= 0);
    if ((e & 31) == 0) g_mask1[e >> 5] = w;
}

__global__ void k_mask2(uint32_t a0, uint32_t a1, uint32_t b0, uint32_t b1)
{
    int e = blockIdx.x * blockDim.x + threadIdx.x;
    uint32_t pa = tf_bits(a0, a1, (uint32_t)e);
    uint32_t pb = tf_bits(b0, b1, (uint32_t)e);
    uint32_t w2 = __ballot_sync(0xffffffffu, (int)pa >= 0);
    uint32_t w3 = __ballot_sync(0xffffffffu, (int)pb >= 0);
    if ((e & 31) == 0) {
        g_mask2[e >> 5] = w2;
        g_mask3[e >> 5] = w3;
    }
}

// ---------------- GEMM1 via mma.sync fp16 (single term) ---------------------
__global__ __launch_bounds__(256, 2) void k_gemm1_mma(const float* __restrict__ x)
{
    extern __shared__ char smem[];
    uint32_t sb = smem_u32(smem);
    const int tid  = threadIdx.x;
    const int wid  = tid >> 5;
    const int lane = tid & 31;
    const int bm   = blockIdx.y * 128;
    const int bn   = blockIdx.x;

    const int arow  = tid >> 1;
    const int ahalf = tid & 1;
    int agr = bm + arow; if (agr >= NN) agr = NN - 1;
    int aod = g_outdeg[agr]; if (aod < 1) aod = 1;
    const float as_ = 2.0f * rsqrtf((float)aod);
    const float* axp = x + (size_t)agr * 512 + ahalf * 16;
    const uint32_t aabase = sb + arow * 80 + ahalf * 32;

    const int m0 = (wid & 3) * 32;
    const int n0 = (wid >> 2) * 64;
    const int la_row  = lane & 15;
    const int la_colq = (lane >> 4) * 16;
    const int lb_row  = ((lane >> 4) << 3) + (lane & 7);
    const int lb_colq = ((lane >> 3) & 1) * 16;

#define LOAD_CHUNK(CH, BUF)                                                    \
    {                                                                          \
        int ch_ = (CH);                                                        \
        const float4* xp = reinterpret_cast<const float4*>(axp + ch_ * 32);    \
        uint32_t mw = g_mask1[((size_t)agr * 512 + ch_ * 32) >> 5]             \
                      >> (ahalf * 16);                                         \
        uint32_t h16[8];                                                       \
        _Pragma("unroll")                                                      \
        for (int p = 0; p < 4; p++) {                                          \
            float4 v = xp[p];                                                  \
            float e0 = ((mw >> (4 * p + 0)) & 1u) ? v.x * as_ : 0.f;           \
            float e1 = ((mw >> (4 * p + 1)) & 1u) ? v.y * as_ : 0.f;           \
            float e2 = ((mw >> (4 * p + 2)) & 1u) ? v.z * as_ : 0.f;           \
            float e3 = ((mw >> (4 * p + 3)) & 1u) ? v.w * as_ : 0.f;           \
            __half2 p0 = __floats2half2_rn(e0, e1);                            \
            __half2 p1 = __floats2half2_rn(e2, e3);                            \
            h16[2 * p]     = *reinterpret_cast<uint32_t*>(&p0);                \
            h16[2 * p + 1] = *reinterpret_cast<uint32_t*>(&p1);                \
        }                                                                      \
        uint32_t aa = aabase + SA_B(BUF);                                      \
        asm volatile("st.shared.v4.b32 [%0], {%1,%2,%3,%4};"                   \
            :: "r"(aa),      "r"(h16[0]), "r"(h16[1]), "r"(h16[2]), "r"(h16[3]) : "memory"); \
        asm volatile("st.shared.v4.b32 [%0], {%1,%2,%3,%4};"                   \
            :: "r"(aa + 16), "r"(h16[4]), "r"(h16[5]), "r"(h16[6]), "r"(h16[7]) : "memory"); \
        _Pragma("unroll")                                                      \
        for (int v2 = 0; v2 < 2; v2++) {                                       \
            int unit = tid + 256 * v2;                                         \
            int n = unit >> 2, uu = unit & 3;                                  \
            size_t gsrc = (size_t)((ch_ * 256 + bn * 128 + n) * 40 + uu * 8);  \
            uint4 hv = *reinterpret_cast<const uint4*>(&g_W1t[gsrc]);          \
            uint32_t ba = sb + SB_B(BUF) + n * 80 + uu * 16;                   \
            asm volatile("st.shared.v4.b32 [%0], {%1,%2,%3,%4};"               \
                :: "r"(ba), "r"(hv.x), "r"(hv.y), "r"(hv.z), "r"(hv.w) : "memory"); \
        }                                                                      \
    }

    float c[2][8][4] = {};

    LOAD_CHUNK(0, 0)
    __syncthreads();

    for (int ch = 0; ch < 16; ch++) {
        int buf = ch & 1;
        if (ch + 1 < 16) LOAD_CHUNK(ch + 1, buf ^ 1)

#pragma unroll
        for (int ks = 0; ks < 2; ks++) {
            int kb2 = ks * 32;
            uint32_t ah[2][4];
#pragma unroll
            for (int mt = 0; mt < 2; mt++) {
                uint32_t aaddr = sb + SA_B(buf) +
                    (m0 + mt * 16 + la_row) * 80 + kb2 + la_colq;
                LDSM4(ah[mt], aaddr);
            }
#pragma unroll
            for (int np = 0; np < 4; np++) {
                uint32_t baddr = sb + SB_B(buf) +
                    (n0 + np * 16 + lb_row) * 80 + kb2 + lb_colq;
                uint32_t bh[4];
                LDSM4(bh, baddr);
#pragma unroll
                for (int mt = 0; mt < 2; mt++) {
                    MMAF16(c[mt][2 * np],     ah[mt], bh[0], bh[1]);
                    MMAF16(c[mt][2 * np + 1], ah[mt], bh[2], bh[3]);
                }
            }
        }
        __syncthreads();
    }

    const int g   = lane >> 2;
    const int tig = lane & 3;
#pragma unroll
    for (int mt = 0; mt < 2; mt++) {
#pragma unroll
        for (int nt = 0; nt < 8; nt++) {
            int col = bn * 128 + n0 + nt * 8 + tig * 2;
            int r0 = bm + m0 + mt * 16 + g;
            if (r0 < NN)
                *reinterpret_cast<__half2*>(&g_t1h[(size_t)r0 * 256 + col]) =
                    __floats2half2_rn(c[mt][nt][0], c[mt][nt][1]);
            int r1 = r0 + 8;
            if (r1 < NN)
                *reinterpret_cast<__half2*>(&g_t1h[(size_t)r1 * 256 + col]) =
                    __floats2half2_rn(c[mt][nt][2], c[mt][nt][3]);
        }
    }
#undef LOAD_CHUNK
}

// ---------------- agg1: single pass fp16 in, fp16 h out ----------------------
__global__ void k_agg1()
{
    int gw   = (blockIdx.x * blockDim.x + threadIdx.x) >> 5;
    int lane = threadIdx.x & 31;
    if (gw >= NN) return;
    int beg = g_off[gw], end = g_off[gw + 1];
    float acc[8] = {};
    const uint4* base = reinterpret_cast<const uint4*>(g_t1h) + lane;
    int e = beg;
    for (; e + 1 < end; e += 2) {
        int s0 = __ldg(&g_csr[e]);
        int s1 = __ldg(&g_csr[e + 1]);
        uint4 v0 = base[(size_t)s0 * 32];
        uint4 v1 = base[(size_t)s1 * 32];
        const __half2* h0 = reinterpret_cast<const __half2*>(&v0);
        const __half2* h1 = reinterpret_cast<const __half2*>(&v1);
#pragma unroll
        for (int q = 0; q < 4; q++) {
            float2 f0 = __half22float2(h0[q]);
            float2 f1 = __half22float2(h1[q]);
            acc[2 * q]     += f0.x + f1.x;
            acc[2 * q + 1] += f0.y + f1.y;
        }
    }
    if (e < end) {
        int s0 = __ldg(&g_csr[e]);
        uint4 v0 = base[(size_t)s0 * 32];
        const __half2* h0 = reinterpret_cast<const __half2*>(&v0);
#pragma unroll
        for (int q = 0; q < 4; q++) {
            float2 f0 = __half22float2(h0[q]);
            acc[2 * q]     += f0.x;
            acc[2 * q + 1] += f0.y;
        }
    }
    float sc = g_in_is[gw];
    __half2 o[4];
#pragma unroll
    for (int q = 0; q < 4; q++)
        o[q] = __floats2half2_rn(fmaxf(acc[2 * q] * sc, 0.f),
                                 fmaxf(acc[2 * q + 1] * sc, 0.f));
    *reinterpret_cast<uint4*>(&g_h2[(size_t)gw * 256 + lane * 8]) =
        *reinterpret_cast<uint4*>(o);
}

// ---------------- BN stats (deterministic, fp16 h) ---------------------------
__global__ void k_bnstats()
{
    int c = threadIdx.x;
    float s = 0.f, ss = 0.f;
    for (int r = blockIdx.x; r < NN; r += 512) {
        float v = __half2float(g_h2[(size_t)r * 256 + c]);
        s += v;
        ss = fmaf(v, v, ss);
    }
    g_part[blockIdx.x * 512 + c]       = s;
    g_part[blockIdx.x * 512 + 256 + c] = ss;
}

__global__ void k_bnreduce()
{
    int j = blockIdx.x * 256 + threadIdx.x;
    float s = 0.f;
    for (int b = 0; b < 512; b++) s += g_part[b * 512 + j];
    g_stats[j] = s;
}

// ---------------- GEMM2/3 fused with BN + dropout mask arrays ---------------
__global__ __launch_bounds__(256) void k_gemm23(const float* __restrict__ W2,
                                                const float* __restrict__ W3)
{
    __shared__ float sA2[32][68];
    __shared__ float sA3[32][68];
    __shared__ float sB [32][36];
    __shared__ float sMean[256], sIstd[256], sScale[64];
    int tid = threadIdx.x;
    int bm = blockIdx.x * 64;
    int c  = tid & 31;
    int rg = tid >> 5;

    {
        float sum  = g_stats[tid];
        float sums = g_stats[256 + tid];
        float m    = sum * (1.0f / NN);
        float var  = sums * (1.0f / NN) - m * m;
        sMean[tid] = m;
        sIstd[tid] = rsqrtf(var + 1e-5f);
        if (tid < 64) {
            int gr = bm + tid;
            sScale[tid] = 2.0f * g_out_is[gr < NN ? gr : NN - 1];
        }
    }
    __syncthreads();

    float acc[8] = {};
    for (int kt = 0; kt < 256; kt += 32) {
        for (int i = tid; i < 2048; i += 256) {
            int r = i >> 5, k = i & 31;
            int gr = bm + r;
            float a2 = 0.f, a3 = 0.f;
            if (gr < NN) {
                size_t gi = (size_t)gr * 256 + kt + k;
                float hv = __half2float(g_h2[gi]);
                float hbn = (hv - sMean[kt + k]) * sIstd[kt + k] * sScale[r];
                uint32_t w2 = g_mask2[gi >> 5];
                uint32_t w3 = g_mask3[gi >> 5];
                a2 = ((w2 >> (k & 31)) & 1u) ? hbn : 0.f;
                a3 = ((w3 >> (k & 31)) & 1u) ? hbn : 0.f;
            }
            sA2[k][r] = a2;
            sA3[k][r] = a3;
        }
        {
            int i = tid;
#pragma unroll
            for (int q = 0; q < 4; q++, i += 256) {
                int k = i >> 5, cc = i & 31;
                int gk = kt + k;
                sB[k][cc] = (cc < 16) ? W2[gk * 16 + cc] : W3[gk * 16 + cc - 16];
            }
        }
        __syncthreads();
        const float* sAx = (c < 16) ? &sA2[0][0] : &sA3[0][0];
#pragma unroll
        for (int kk = 0; kk < 32; kk++) {
            float b = sB[kk][c];
            const float4* pa = reinterpret_cast<const float4*>(sAx + kk * 68 + rg * 8);
            float4 v0 = pa[0], v1 = pa[1];
            acc[0] = fmaf(v0.x, b, acc[0]);
            acc[1] = fmaf(v0.y, b, acc[1]);
            acc[2] = fmaf(v0.z, b, acc[2]);
            acc[3] = fmaf(v0.w, b, acc[3]);
            acc[4] = fmaf(v1.x, b, acc[4]);
            acc[5] = fmaf(v1.y, b, acc[5]);
            acc[6] = fmaf(v1.z, b, acc[6]);
            acc[7] = fmaf(v1.w, b, acc[7]);
        }
        __syncthreads();
    }
#pragma unroll
    for (int i = 0; i < 8; i++) {
        int gr = bm + rg * 8 + i;
        if (gr < NN) g_mulv_pre[gr * 32 + c] = acc[i];
    }
}

// ---------------- agg2 --------------------------------------------------------
__global__ void k_agg2()
{
    int gw   = (blockIdx.x * blockDim.x + threadIdx.x) >> 5;
    int lane = threadIdx.x & 31;
    if (gw >= NN) return;
    int beg = g_off[gw], end = g_off[gw + 1];
    float acc = 0.f;
    int e = beg;
    for (; e + 1 < end; e += 2) {
        int s0 = __ldg(&g_csr[e]);
        int s1 = __ldg(&g_csr[e + 1]);
        acc += g_mulv_pre[s0 * 32 + lane];
        acc += g_mulv_pre[s1 * 32 + lane];
    }
    if (e < end) {
        int s0 = __ldg(&g_csr[e]);
        acc += g_mulv_pre[s0 * 32 + lane];
    }
    g_mulv[gw * 32 + lane] = acc * g_in_is[gw];
}

// ---------------- reparameterize ----------------------------------------------
__global__ void k_reparam(float* __restrict__ out, uint32_t k0, uint32_t k1)
{
    int i = blockIdx.x * blockDim.x + threadIdx.x;
    int e = i * 4;
    if (e >= NN * NCLS) return;
    int row = e >> 4;
    int c   = e & 15;
    const float* mrow = &g_mulv[row * 32];
    float4 mu = *reinterpret_cast<const float4*>(&mrow[c]);
    float4 lv = *reinterpret_cast<const float4*>(&mrow[16 + c]);
    float mus[4] = { mu.x, mu.y, mu.z, mu.w };
    float lvs[4] = { lv.x, lv.y, lv.z, lv.w };
    float r[4];
#pragma unroll
    for (int q = 0; q < 4; q++) {
        uint32_t bits = tf_bits(k0, k1, (uint32_t)(e + q));
        float f = __uint_as_float((bits >> 9) | 0x3f800000u) - 1.0f;
        float u = f * 2.0f - 0.99999994f;
        float eps = 1.4142135623730951f * erfinvf(u);
        r[q] = eps * expf(lvs[q]) + mus[q];
    }
    *reinterpret_cast<float4*>(&out[e]) = make_float4(r[0], r[1], r[2], r[3]);
}

// ---------------- launch --------------------------------------------------------
extern "C" void kernel_launch(void* const* d_in, const int* in_sizes, int n_in,
                              void* d_out, int out_size)
{
    const float* x    = (const float*)d_in[0];
    const float* W1   = (const float*)d_in[1];
    const float* W2   = (const float*)d_in[2];
    const float* W3   = (const float*)d_in[3];
    const int*   esrc = (const int*)d_in[4];
    const int*   edst = (const int*)d_in[5];
    float*       out  = (float*)d_out;

    uint32_t k1a, k1b, k2a0, k2a1, k2b0, k2b1, ke0, ke1;
    tf2x32(0u, 42u, 0u, 0u, k1a,  k1b);
    tf2x32(0u, 42u, 0u, 1u, k2a0, k2a1);
    tf2x32(0u, 42u, 0u, 2u, k2b0, k2b1);
    tf2x32(0u, 42u, 0u, 3u, ke0,  ke1);

    static cudaStream_t s1 = nullptr, s2 = nullptr;
    static cudaEvent_t evP = nullptr, evDeg = nullptr, evCsr = nullptr,
                       evG1 = nullptr, evM23 = nullptr;
    if (!s1) {
        cudaStreamCreateWithFlags(&s1, cudaStreamNonBlocking);
        cudaStreamCreateWithFlags(&s2, cudaStreamNonBlocking);
        cudaEventCreateWithFlags(&evP,   cudaEventDisableTiming);
        cudaEventCreateWithFlags(&evDeg, cudaEventDisableTiming);
        cudaEventCreateWithFlags(&evCsr, cudaEventDisableTiming);
        cudaEventCreateWithFlags(&evG1,  cudaEventDisableTiming);
        cudaEventCreateWithFlags(&evM23, cudaEventDisableTiming);
        cudaFuncSetAttribute(k_gemm1_mma,
                             cudaFuncAttributeMaxDynamicSharedMemorySize, SM_TOT);
    }

    // s0: prep; fork s1 for graph build
    k_prep<<<(INDIM * HIDD) / 256, 256>>>(W1);
    cudaEventRecord(evP, 0);
    cudaStreamWaitEvent(s1, evP, 0);

    // s1: deg -> scan -> csrfill     (L2-bound chain)
    k_deg    <<<EE / 256, 256, 0, s1>>>(esrc, edst);
    cudaEventRecord(evDeg, s1);
    k_scan1  <<<SCAN_B, 1024, 0, s1>>>();
    k_scan2  <<<1, 128, 0, s1>>>();
    k_scan3  <<<(NN + 1023) / 1024, 1024, 0, s1>>>();
    k_csrfill<<<EE / 256, 256, 0, s1>>>(esrc, edst);
    cudaEventRecord(evCsr, s1);

    // s0: mask1 (ALU, overlaps deg) -> gemm1 (overlaps scan+csrfill)
    k_mask1<<<NN * INDIM / 256, 256>>>(k1a, k1b);
    cudaStreamWaitEvent(0, evDeg, 0);        // gemm1 reads g_outdeg
    dim3 g1(2, (NN + 127) / 128);
    k_gemm1_mma<<<g1, 256, SM_TOT>>>(x);
    cudaEventRecord(evG1, 0);

    // s2: mask2/3 (ALU) after gemm1 -> overlaps agg1 (L2-bound)
    cudaStreamWaitEvent(s2, evG1, 0);
    k_mask2<<<NN * HIDD / 256, 256, 0, s2>>>(k2a0, k2a1, k2b0, k2b1);
    cudaEventRecord(evM23, s2);

    // s0: aggregation path
    cudaStreamWaitEvent(0, evCsr, 0);
    k_agg1   <<<(NN * 32) / 256, 256>>>();

    k_bnstats <<<512, 256>>>();
    k_bnreduce<<<2, 256>>>();

    cudaStreamWaitEvent(0, evM23, 0);
    k_gemm23 <<<(NN + 63) / 64, 256>>>(W2, W3);
    k_agg2   <<<(NN * 32) / 256, 256>>>();

    k_reparam<<<(NN * NCLS / 4 + 255) / 256, 256>>>(out, ke0, ke1);
}

// round 16
// speedup vs baseline: 1.1458x; 1.0003x over previous
#include <cuda_runtime.h>
#include <cuda_bf16.h>
#include <cuda_fp16.h>
#include <stdint.h>

#define NN      100000
#define EE      3200000
#define INDIM   512
#define HIDD    256
#define NCLS    16
#define SCAN_B  98            // ceil(NN/1024)

// ---------------- static device scratch ------------------------------------
__device__ __half   g_t1h[(size_t)NN * HIDD];     // fp16 t1
__device__ __half   g_h2 [(size_t)NN * HIDD];     // fp16 h
__device__ __half   g_mulv_preh[NN * 32];         // fp16 mu|logvar pre-agg
__device__ uint32_t g_mask1[(size_t)NN * INDIM / 32];
__device__ uint32_t g_mask2[(size_t)NN * HIDD / 32];
__device__ uint32_t g_mask3[(size_t)NN * HIDD / 32];
__device__ int      g_outdeg[NN];
__device__ int      g_indeg [NN];
__device__ int      g_fill  [NN];
__device__ int      g_off   [NN + 1];
__device__ int      g_bsum  [SCAN_B];
__device__ int      g_csr   [EE];
__device__ float    g_in_is [NN];
__device__ float    g_out_is[NN];
__device__ float    g_part  [512 * 512];
__device__ float    g_stats [512];
// W1 transposed fp16: [16 chunks][256 n][40 k-ushorts (32 data + 8 pad)]
__device__ unsigned short g_W1t[16 * 256 * 40];

// smem layout of k_gemm1_mma (dynamic, bytes): A buf0/1, B buf0/1
#define SA_B(b) ((b) * 10240)
#define SB_B(b) (20480 + (b) * 10240)
#define SM_TOT  40960

#define LDSM4(R, ADDR)                                                         \
    asm volatile("ldmatrix.sync.aligned.m8n8.x4.shared.b16 {%0,%1,%2,%3}, [%4];" \
        : "=r"((R)[0]), "=r"((R)[1]), "=r"((R)[2]), "=r"((R)[3]) : "r"(ADDR))

#define MMAF16(C, A, B0, B1)                                                   \
    asm volatile("mma.sync.aligned.m16n8k16.row.col.f32.f16.f16.f32 "          \
        "{%0,%1,%2,%3}, {%4,%5,%6,%7}, {%8,%9}, {%0,%1,%2,%3};"                \
        : "+f"((C)[0]), "+f"((C)[1]), "+f"((C)[2]), "+f"((C)[3])               \
        : "r"((A)[0]), "r"((A)[1]), "r"((A)[2]), "r"((A)[3]), "r"(B0), "r"(B1))

__device__ __forceinline__ uint32_t smem_u32(const void* p)
{
    uint32_t a;
    asm("{ .reg .u64 t; cvta.to.shared.u64 t, %1; cvt.u32.u64 %0, t; }"
        : "=r"(a) : "l"(p));
    return a;
}

// ---------------- threefry2x32 (JAX-exact core) -----------------------------
__host__ __device__ __forceinline__ uint32_t tf_rot(uint32_t v, int r)
{
#if defined(__CUDA_ARCH__)
    return __funnelshift_l(v, v, r);
#else
    return (v << r) | (v >> (32 - r));
#endif
}

__host__ __device__ __forceinline__ void tf2x32(uint32_t k0, uint32_t k1,
                                                uint32_t x0, uint32_t x1,
                                                uint32_t &o0, uint32_t &o1)
{
    uint32_t ks2 = k0 ^ k1 ^ 0x1BD11BDAu;
#define TF_RND(r) { x0 += x1; x1 = tf_rot(x1, r); x1 ^= x0; }
    x0 += k0; x1 += k1;
    TF_RND(13) TF_RND(15) TF_RND(26) TF_RND(6)
    x0 += k1;  x1 += ks2 + 1u;
    TF_RND(17) TF_RND(29) TF_RND(16) TF_RND(24)
    x0 += ks2; x1 += k0 + 2u;
    TF_RND(13) TF_RND(15) TF_RND(26) TF_RND(6)
    x0 += k0;  x1 += k1 + 3u;
    TF_RND(17) TF_RND(29) TF_RND(16) TF_RND(24)
    x0 += k1;  x1 += ks2 + 4u;
    TF_RND(13) TF_RND(15) TF_RND(26) TF_RND(6)
    x0 += ks2; x1 += k0 + 5u;
    o0 = x0; o1 = x1;
#undef TF_RND
}

__device__ __forceinline__ uint32_t tf_bits(uint32_t k0, uint32_t k1, uint32_t j)
{
    uint32_t o0, o1;
    tf2x32(k0, k1, 0u, j, o0, o1);
    return o0 ^ o1;
}

// ---------------- setup kernels ----------------------------------------------
__global__ void k_zero()
{
    int i = blockIdx.x * blockDim.x + threadIdx.x;
    if (i < NN) { g_outdeg[i] = 0; g_indeg[i] = 0; }
}

__global__ void k_w1t(const float* __restrict__ W1)
{
    int i = blockIdx.x * blockDim.x + threadIdx.x;
    if (i < INDIM * HIDD) {
        int k = i >> 8, n = i & 255;
        int ch = k >> 5, kk = k & 31;
        int idx = (ch * 256 + n) * 40 + kk;
        g_W1t[idx] = __half_as_ushort(__float2half_rn(W1[i]));
    }
}

__global__ void k_deg(const int* __restrict__ src, const int* __restrict__ dst)
{
    int e = blockIdx.x * blockDim.x + threadIdx.x;
    if (e < EE) {
        atomicAdd(&g_outdeg[src[e]], 1);
        atomicAdd(&g_indeg [dst[e]], 1);
    }
}

// ---------------- multi-block scan of indeg -> g_off -------------------------
__global__ void k_scan1()
{
    __shared__ int warpsum[32];
    int tid = threadIdx.x, lane = tid & 31, wid = tid >> 5;
    int i = blockIdx.x * 1024 + tid;
    int v = (i < NN) ? g_indeg[i] : 0;
    int incl = v;
#pragma unroll
    for (int o = 1; o < 32; o <<= 1) {
        int n = __shfl_up_sync(0xffffffffu, incl, o);
        if (lane >= o) incl += n;
    }
    if (lane == 31) warpsum[wid] = incl;
    __syncthreads();
    if (wid == 0) {
        int s = warpsum[lane];
#pragma unroll
        for (int o = 1; o < 32; o <<= 1) {
            int n = __shfl_up_sync(0xffffffffu, s, o);
            if (lane >= o) s += n;
        }
        warpsum[lane] = s;
    }
    __syncthreads();
    int wpre = (wid > 0) ? warpsum[wid - 1] : 0;
    if (i < NN) g_off[i] = wpre + incl - v;
    if (tid == 1023) g_bsum[blockIdx.x] = wpre + incl;
}

__global__ void k_scan2()
{
    __shared__ int sh[SCAN_B];
    int tid = threadIdx.x;
    int v = (tid < SCAN_B) ? g_bsum[tid] : 0;
    if (tid < SCAN_B) sh[tid] = v;
    __syncthreads();
    if (tid == 0) {
        int run = 0;
        for (int b = 0; b < SCAN_B; b++) {
            int t = sh[b];
            sh[b] = run;
            run += t;
        }
        g_off[NN] = run;
    }
    __syncthreads();
    if (tid < SCAN_B) g_bsum[tid] = sh[tid];
}

__global__ void k_scan3()
{
    int i = blockIdx.x * blockDim.x + threadIdx.x;
    if (i < NN) {
        int off = g_off[i] + g_bsum[i >> 10];
        g_off[i]  = off;
        g_fill[i] = off;                 // running fill pointer for csrfill
        int od = g_outdeg[i]; if (od < 1) od = 1;
        int id = g_indeg [i]; if (id < 1) id = 1;
        g_out_is[i] = rsqrtf((float)od);
        g_in_is [i] = rsqrtf((float)id);
    }
}

__global__ void k_csrfill(const int* __restrict__ src, const int* __restrict__ dst)
{
    int e = blockIdx.x * blockDim.x + threadIdx.x;
    if (e < EE) {
        int p = atomicAdd(&g_fill[dst[e]], 1);
        g_csr[p] = src[e];
    }
}

// ---------------- dropout bitmasks -------------------------------------------
__global__ void k_mask1(uint32_t ka, uint32_t kb)
{
    int e = blockIdx.x * blockDim.x + threadIdx.x;
    uint32_t bits = tf_bits(ka, kb, (uint32_t)e);
    uint32_t w = __ballot_sync(0xffffffffu, (int)bits >= 0);
    if ((e & 31) == 0) g_mask1[e >> 5] = w;
}

__global__ void k_mask2(uint32_t a0, uint32_t a1, uint32_t b0, uint32_t b1)
{
    int e = blockIdx.x * blockDim.x + threadIdx.x;
    uint32_t pa = tf_bits(a0, a1, (uint32_t)e);
    uint32_t pb = tf_bits(b0, b1, (uint32_t)e);
    uint32_t w2 = __ballot_sync(0xffffffffu, (int)pa >= 0);
    uint32_t w3 = __ballot_sync(0xffffffffu, (int)pb >= 0);
    if ((e & 31) == 0) {
        g_mask2[e >> 5] = w2;
        g_mask3[e >> 5] = w3;
    }
}

// ---------------- GEMM1 via mma.sync fp16 (single term) ---------------------
__global__ __launch_bounds__(256, 2) void k_gemm1_mma(const float* __restrict__ x)
{
    extern __shared__ char smem[];
    uint32_t sb = smem_u32(smem);
    const int tid  = threadIdx.x;
    const int wid  = tid >> 5;
    const int lane = tid & 31;
    const int bm   = blockIdx.y * 128;
    const int bn   = blockIdx.x;

    const int arow  = tid >> 1;
    const int ahalf = tid & 1;
    int agr = bm + arow; if (agr >= NN) agr = NN - 1;
    int aod = g_outdeg[agr]; if (aod < 1) aod = 1;
    const float as_ = 2.0f * rsqrtf((float)aod);
    const float* axp = x + (size_t)agr * 512 + ahalf * 16;
    const uint32_t aabase = sb + arow * 80 + ahalf * 32;

    const int m0 = (wid & 3) * 32;
    const int n0 = (wid >> 2) * 64;
    const int la_row  = lane & 15;
    const int la_colq = (lane >> 4) * 16;
    const int lb_row  = ((lane >> 4) << 3) + (lane & 7);
    const int lb_colq = ((lane >> 3) & 1) * 16;

#define LOAD_CHUNK(CH, BUF)                                                    \
    {                                                                          \
        int ch_ = (CH);                                                        \
        const float4* xp = reinterpret_cast<const float4*>(axp + ch_ * 32);    \
        uint32_t mw = g_mask1[((size_t)agr * 512 + ch_ * 32) >> 5]             \
                      >> (ahalf * 16);                                         \
        uint32_t h16[8];                                                       \
        _Pragma("unroll")                                                      \
        for (int p = 0; p < 4; p++) {                                          \
            float4 v = xp[p];                                                  \
            float e0 = ((mw >> (4 * p + 0)) & 1u) ? v.x * as_ : 0.f;           \
            float e1 = ((mw >> (4 * p + 1)) & 1u) ? v.y * as_ : 0.f;           \
            float e2 = ((mw >> (4 * p + 2)) & 1u) ? v.z * as_ : 0.f;           \
            float e3 = ((mw >> (4 * p + 3)) & 1u) ? v.w * as_ : 0.f;           \
            __half2 p0 = __floats2half2_rn(e0, e1);                            \
            __half2 p1 = __floats2half2_rn(e2, e3);                            \
            h16[2 * p]     = *reinterpret_cast<uint32_t*>(&p0);                \
            h16[2 * p + 1] = *reinterpret_cast<uint32_t*>(&p1);                \
        }                                                                      \
        uint32_t aa = aabase + SA_B(BUF);                                      \
        asm volatile("st.shared.v4.b32 [%0], {%1,%2,%3,%4};"                   \
            :: "r"(aa),      "r"(h16[0]), "r"(h16[1]), "r"(h16[2]), "r"(h16[3]) : "memory"); \
        asm volatile("st.shared.v4.b32 [%0], {%1,%2,%3,%4};"                   \
            :: "r"(aa + 16), "r"(h16[4]), "r"(h16[5]), "r"(h16[6]), "r"(h16[7]) : "memory"); \
        _Pragma("unroll")                                                      \
        for (int v2 = 0; v2 < 2; v2++) {                                       \
            int unit = tid + 256 * v2;                                         \
            int n = unit >> 2, uu = unit & 3;                                  \
            size_t gsrc = (size_t)((ch_ * 256 + bn * 128 + n) * 40 + uu * 8);  \
            uint4 hv = *reinterpret_cast<const uint4*>(&g_W1t[gsrc]);          \
            uint32_t ba = sb + SB_B(BUF) + n * 80 + uu * 16;                   \
            asm volatile("st.shared.v4.b32 [%0], {%1,%2,%3,%4};"               \
                :: "r"(ba), "r"(hv.x), "r"(hv.y), "r"(hv.z), "r"(hv.w) : "memory"); \
        }                                                                      \
    }

    float c[2][8][4] = {};

    LOAD_CHUNK(0, 0)
    __syncthreads();

    for (int ch = 0; ch < 16; ch++) {
        int buf = ch & 1;
        if (ch + 1 < 16) LOAD_CHUNK(ch + 1, buf ^ 1)

#pragma unroll
        for (int ks = 0; ks < 2; ks++) {
            int kb2 = ks * 32;
            uint32_t ah[2][4];
#pragma unroll
            for (int mt = 0; mt < 2; mt++) {
                uint32_t aaddr = sb + SA_B(buf) +
                    (m0 + mt * 16 + la_row) * 80 + kb2 + la_colq;
                LDSM4(ah[mt], aaddr);
            }
#pragma unroll
            for (int np = 0; np < 4; np++) {
                uint32_t baddr = sb + SB_B(buf) +
                    (n0 + np * 16 + lb_row) * 80 + kb2 + lb_colq;
                uint32_t bh[4];
                LDSM4(bh, baddr);
#pragma unroll
                for (int mt = 0; mt < 2; mt++) {
                    MMAF16(c[mt][2 * np],     ah[mt], bh[0], bh[1]);
                    MMAF16(c[mt][2 * np + 1], ah[mt], bh[2], bh[3]);
                }
            }
        }
        __syncthreads();
    }

    const int g   = lane >> 2;
    const int tig = lane & 3;
#pragma unroll
    for (int mt = 0; mt < 2; mt++) {
#pragma unroll
        for (int nt = 0; nt < 8; nt++) {
            int col = bn * 128 + n0 + nt * 8 + tig * 2;
            int r0 = bm + m0 + mt * 16 + g;
            if (r0 < NN)
                *reinterpret_cast<__half2*>(&g_t1h[(size_t)r0 * 256 + col]) =
                    __floats2half2_rn(c[mt][nt][0], c[mt][nt][1]);
            int r1 = r0 + 8;
            if (r1 < NN)
                *reinterpret_cast<__half2*>(&g_t1h[(size_t)r1 * 256 + col]) =
                    __floats2half2_rn(c[mt][nt][2], c[mt][nt][3]);
        }
    }
#undef LOAD_CHUNK
}

// ---------------- agg1: single pass fp16 in, fp16 h out ----------------------
__global__ void k_agg1()
{
    int gw   = (blockIdx.x * blockDim.x + threadIdx.x) >> 5;
    int lane = threadIdx.x & 31;
    if (gw >= NN) return;
    int beg = g_off[gw], end = g_off[gw + 1];
    float acc[8] = {};
    const uint4* base = reinterpret_cast<const uint4*>(g_t1h) + lane;
    int e = beg;
    for (; e + 1 < end; e += 2) {
        int s0 = __ldg(&g_csr[e]);
        int s1 = __ldg(&g_csr[e + 1]);
        uint4 v0 = base[(size_t)s0 * 32];
        uint4 v1 = base[(size_t)s1 * 32];
        const __half2* h0 = reinterpret_cast<const __half2*>(&v0);
        const __half2* h1 = reinterpret_cast<const __half2*>(&v1);
#pragma unroll
        for (int q = 0; q < 4; q++) {
            float2 f0 = __half22float2(h0[q]);
            float2 f1 = __half22float2(h1[q]);
            acc[2 * q]     += f0.x + f1.x;
            acc[2 * q + 1] += f0.y + f1.y;
        }
    }
    if (e < end) {
        int s0 = __ldg(&g_csr[e]);
        uint4 v0 = base[(size_t)s0 * 32];
        const __half2* h0 = reinterpret_cast<const __half2*>(&v0);
#pragma unroll
        for (int q = 0; q < 4; q++) {
            float2 f0 = __half22float2(h0[q]);
            acc[2 * q]     += f0.x;
            acc[2 * q + 1] += f0.y;
        }
    }
    float sc = g_in_is[gw];
    __half2 o[4];
#pragma unroll
    for (int q = 0; q < 4; q++)
        o[q] = __floats2half2_rn(fmaxf(acc[2 * q] * sc, 0.f),
                                 fmaxf(acc[2 * q + 1] * sc, 0.f));
    *reinterpret_cast<uint4*>(&g_h2[(size_t)gw * 256 + lane * 8]) =
        *reinterpret_cast<uint4*>(o);
}

// ---------------- BN stats (deterministic, fp16 h) ---------------------------
__global__ void k_bnstats()
{
    int c = threadIdx.x;
    float s = 0.f, ss = 0.f;
    for (int r = blockIdx.x; r < NN; r += 512) {
        float v = __half2float(g_h2[(size_t)r * 256 + c]);
        s += v;
        ss = fmaf(v, v, ss);
    }
    g_part[blockIdx.x * 512 + c]       = s;
    g_part[blockIdx.x * 512 + 256 + c] = ss;
}

__global__ void k_bnreduce()
{
    int j = blockIdx.x * 256 + threadIdx.x;
    float s = 0.f;
    for (int b = 0; b < 512; b++) s += g_part[b * 512 + j];
    g_stats[j] = s;
}

// ---------------- GEMM2/3 fused with BN + dropout mask arrays ---------------
__global__ __launch_bounds__(256) void k_gemm23(const float* __restrict__ W2,
                                                const float* __restrict__ W3)
{
    __shared__ float sA2[32][68];
    __shared__ float sA3[32][68];
    __shared__ float sB [32][36];
    __shared__ float sMean[256], sIstd[256], sScale[64];
    int tid = threadIdx.x;
    int bm = blockIdx.x * 64;
    int c  = tid & 31;
    int rg = tid >> 5;

    {
        float sum  = g_stats[tid];
        float sums = g_stats[256 + tid];
        float m    = sum * (1.0f / NN);
        float var  = sums * (1.0f / NN) - m * m;
        sMean[tid] = m;
        sIstd[tid] = rsqrtf(var + 1e-5f);
        if (tid < 64) {
            int gr = bm + tid;
            sScale[tid] = 2.0f * g_out_is[gr < NN ? gr : NN - 1];
        }
    }
    __syncthreads();

    float acc[8] = {};
    for (int kt = 0; kt < 256; kt += 32) {
        for (int i = tid; i < 2048; i += 256) {
            int r = i >> 5, k = i & 31;
            int gr = bm + r;
            float a2 = 0.f, a3 = 0.f;
            if (gr < NN) {
                size_t gi = (size_t)gr * 256 + kt + k;
                float hv = __half2float(g_h2[gi]);
                float hbn = (hv - sMean[kt + k]) * sIstd[kt + k] * sScale[r];
                uint32_t w2 = g_mask2[gi >> 5];
                uint32_t w3 = g_mask3[gi >> 5];
                a2 = ((w2 >> (k & 31)) & 1u) ? hbn : 0.f;
                a3 = ((w3 >> (k & 31)) & 1u) ? hbn : 0.f;
            }
            sA2[k][r] = a2;
            sA3[k][r] = a3;
        }
        {
            int i = tid;
#pragma unroll
            for (int q = 0; q < 4; q++, i += 256) {
                int k = i >> 5, cc = i & 31;
                int gk = kt + k;
                sB[k][cc] = (cc < 16) ? W2[gk * 16 + cc] : W3[gk * 16 + cc - 16];
            }
        }
        __syncthreads();
        const float* sAx = (c < 16) ? &sA2[0][0] : &sA3[0][0];
#pragma unroll
        for (int kk = 0; kk < 32; kk++) {
            float b = sB[kk][c];
            const float4* pa = reinterpret_cast<const float4*>(sAx + kk * 68 + rg * 8);
            float4 v0 = pa[0], v1 = pa[1];
            acc[0] = fmaf(v0.x, b, acc[0]);
            acc[1] = fmaf(v0.y, b, acc[1]);
            acc[2] = fmaf(v0.z, b, acc[2]);
            acc[3] = fmaf(v0.w, b, acc[3]);
            acc[4] = fmaf(v1.x, b, acc[4]);
            acc[5] = fmaf(v1.y, b, acc[5]);
            acc[6] = fmaf(v1.z, b, acc[6]);
            acc[7] = fmaf(v1.w, b, acc[7]);
        }
        __syncthreads();
    }
#pragma unroll
    for (int i = 0; i < 8; i++) {
        int gr = bm + rg * 8 + i;
        if (gr < NN)
            g_mulv_preh[gr * 32 + c] = __float2half_rn(acc[i]);
    }
}

// ---------------- agg2 + reparameterize fused --------------------------------
__global__ void k_agg2rep(float* __restrict__ out, uint32_t k0, uint32_t k1)
{
    int gw   = (blockIdx.x * blockDim.x + threadIdx.x) >> 5;
    int lane = threadIdx.x & 31;
    if (gw >= NN) return;
    int beg = g_off[gw], end = g_off[gw + 1];
    float acc = 0.f;
    int e = beg;
    for (; e + 1 < end; e += 2) {
        int s0 = __ldg(&g_csr[e]);
        int s1 = __ldg(&g_csr[e + 1]);
        acc += __half2float(g_mulv_preh[s0 * 32 + lane]);
        acc += __half2float(g_mulv_preh[s1 * 32 + lane]);
    }
    if (e < end) {
        int s0 = __ldg(&g_csr[e]);
        acc += __half2float(g_mulv_preh[s0 * 32 + lane]);
    }
    float v = acc * g_in_is[gw];          // lane<16: mu, lane>=16: logvar
    float lv = __shfl_sync(0xffffffffu, v, lane + 16);
    if (lane < 16) {
        uint32_t bits = tf_bits(k0, k1, (uint32_t)(gw * 16 + lane));
        float f = __uint_as_float((bits >> 9) | 0x3f800000u) - 1.0f;
        float u = f * 2.0f - 0.99999994f;
        float eps = 1.4142135623730951f * erfinvf(u);
        out[gw * 16 + lane] = eps * expf(lv) + v;
    }
}

// ---------------- launch --------------------------------------------------------
extern "C" void kernel_launch(void* const* d_in, const int* in_sizes, int n_in,
                              void* d_out, int out_size)
{
    const float* x    = (const float*)d_in[0];
    const float* W1   = (const float*)d_in[1];
    const float* W2   = (const float*)d_in[2];
    const float* W3   = (const float*)d_in[3];
    const int*   esrc = (const int*)d_in[4];
    const int*   edst = (const int*)d_in[5];
    float*       out  = (float*)d_out;

    uint32_t k1a, k1b, k2a0, k2a1, k2b0, k2b1, ke0, ke1;
    tf2x32(0u, 42u, 0u, 0u, k1a,  k1b);
    tf2x32(0u, 42u, 0u, 1u, k2a0, k2a1);
    tf2x32(0u, 42u, 0u, 2u, k2b0, k2b1);
    tf2x32(0u, 42u, 0u, 3u, ke0,  ke1);

    static cudaStream_t s1 = nullptr, s2 = nullptr;
    static cudaEvent_t evP = nullptr, evDeg = nullptr, evCsr = nullptr,
                       evG1 = nullptr, evM23 = nullptr, evW = nullptr;
    if (!s1) {
        cudaStreamCreateWithFlags(&s1, cudaStreamNonBlocking);
        cudaStreamCreateWithFlags(&s2, cudaStreamNonBlocking);
        cudaEventCreateWithFlags(&evP,   cudaEventDisableTiming);
        cudaEventCreateWithFlags(&evDeg, cudaEventDisableTiming);
        cudaEventCreateWithFlags(&evCsr, cudaEventDisableTiming);
        cudaEventCreateWithFlags(&evG1,  cudaEventDisableTiming);
        cudaEventCreateWithFlags(&evM23, cudaEventDisableTiming);
        cudaEventCreateWithFlags(&evW,   cudaEventDisableTiming);
        cudaFuncSetAttribute(k_gemm1_mma,
                             cudaFuncAttributeMaxDynamicSharedMemorySize, SM_TOT);
    }

    // s0: zero deg arrays; record fork event
    k_zero<<<(NN + 255) / 256, 256>>>();
    cudaEventRecord(evP, 0);

    // fork s1 and s2 from origin (REQUIRED for capture legality)
    cudaStreamWaitEvent(s1, evP, 0);
    cudaStreamWaitEvent(s2, evP, 0);

    // s2: W1 fp16 image (off critical path)
    k_w1t<<<(INDIM * HIDD) / 256, 256, 0, s2>>>(W1);
    cudaEventRecord(evW, s2);

    // s1: deg -> scan -> csrfill     (L2-bound chain)
    k_deg    <<<EE / 256, 256, 0, s1>>>(esrc, edst);
    cudaEventRecord(evDeg, s1);
    k_scan1  <<<SCAN_B, 1024, 0, s1>>>();
    k_scan2  <<<1, 128, 0, s1>>>();
    k_scan3  <<<(NN + 1023) / 1024, 1024, 0, s1>>>();
    k_csrfill<<<EE / 256, 256, 0, s1>>>(esrc, edst);
    cudaEventRecord(evCsr, s1);

    // s0: mask1 (ALU, overlaps deg) -> gemm1 (overlaps scan+csrfill)
    k_mask1<<<NN * INDIM / 256, 256>>>(k1a, k1b);
    cudaStreamWaitEvent(0, evDeg, 0);
    cudaStreamWaitEvent(0, evW, 0);
    dim3 g1(2, (NN + 127) / 128);
    k_gemm1_mma<<<g1, 256, SM_TOT>>>(x);
    cudaEventRecord(evG1, 0);

    // s2: mask2/3 (ALU) after gemm1 -> overlaps agg1 (L2-bound)
    cudaStreamWaitEvent(s2, evG1, 0);
    k_mask2<<<NN * HIDD / 256, 256, 0, s2>>>(k2a0, k2a1, k2b0, k2b1);
    cudaEventRecord(evM23, s2);

    // s0: aggregation path
    cudaStreamWaitEvent(0, evCsr, 0);
    k_agg1   <<<(NN * 32) / 256, 256>>>();

    k_bnstats <<<512, 256>>>();
    k_bnreduce<<<2, 256>>>();

    cudaStreamWaitEvent(0, evM23, 0);
    k_gemm23 <<<(NN + 63) / 64, 256>>>(W2, W3);
    k_agg2rep<<<(NN * 32) / 256, 256>>>(out, ke0, ke1);
}